// round 12
// baseline (speedup 1.0000x reference)
#include <cuda_runtime.h>
#include <math.h>
#include <stdint.h>

#define BSZ   4096
#define QSZ   32768
#define DIM   128
#define QSPLIT 2
#define QPART (QSZ / QSPLIT)   // 16384
#define NSEG  4
#define NSEG_COLS (BSZ / NSEG) // 1024

#define INV_T 10.0f
#define SHIFT 10.0f

// ---------------- scratch (static device globals; no allocation) ----------------
__device__ float g_pn [2][BSZ * DIM];
__device__ float g_pnb[2][BSZ * DIM];   // plain layout (k_logits B)
__device__ float g_pnr[2][BSZ * DIM];
__device__ float g_nn [2][BSZ * DIM];
__device__ float g_qb [QSZ * DIM];      // PAIR-PERMUTED k layout (k_nn B)
__device__ float g_qr [QSZ * DIM];
__device__ float g_pval[2][QSPLIT][BSZ];
__device__ int   g_pidx[2][QSPLIT][BSZ];
__device__ float g_rowpart[2][NSEG][BSZ];
__device__ float g_colpart[2][32][BSZ];
__device__ float g_diag[2][BSZ];

// ---------------- helpers ----------------
__device__ __forceinline__ uint32_t smem_u32(const void* p) {
    uint32_t a;
    asm("{ .reg .u64 t; cvta.to.shared.u64 t, %1; cvt.u32.u64 %0, t; }" : "=r"(a) : "l"(p));
    return a;
}
__device__ __forceinline__ uint32_t to_tf32_rna(float x) {
    uint32_t r;
    asm("cvt.rna.tf32.f32 %0, %1;" : "=r"(r) : "f"(x));
    return r;
}
__device__ __forceinline__ void mma_tf32(float c[4], const uint32_t a[4], const uint32_t b[2]) {
    asm volatile(
        "mma.sync.aligned.m16n8k8.row.col.f32.tf32.tf32.f32 "
        "{%0,%1,%2,%3}, {%4,%5,%6,%7}, {%8,%9}, {%0,%1,%2,%3};\n"
        : "+f"(c[0]), "+f"(c[1]), "+f"(c[2]), "+f"(c[3])
        : "r"(a[0]), "r"(a[1]), "r"(a[2]), "r"(a[3]), "r"(b[0]), "r"(b[1]));
}
__device__ __forceinline__ void cp16(uint32_t dst, const void* src) {
    asm volatile("cp.async.cg.shared.global [%0], [%1], 16;" :: "r"(dst), "l"(src) : "memory");
}
#define CP_COMMIT() asm volatile("cp.async.commit_group;" ::: "memory")
#define CP_WAIT(n)  asm volatile("cp.async.wait_group %0;" :: "n"(n) : "memory")

// ---------------- K0: split queue into big/res, PAIR-PERMUTED within k-groups of 8 ----------------
// out[2t] = in[t], out[2t+1] = in[t+4]  (within each group of 8 k values)
__global__ void k_qsplit(const float* __restrict__ queue) {
    int i = blockIdx.x * blockDim.x + threadIdx.x;    // one group of 8 per thread
    if (i >= QSZ * DIM / 8) return;
    const float* src = queue + (size_t)i * 8;
    float4 lo = *(const float4*)(src);
    float4 hi = *(const float4*)(src + 4);
    float p[8] = { lo.x, hi.x, lo.y, hi.y, lo.z, hi.z, lo.w, hi.w };
    float b[8], r[8];
#pragma unroll
    for (int t = 0; t < 8; t++) {
        b[t] = __uint_as_float(to_tf32_rna(p[t]));
        r[t] = p[t] - b[t];
    }
    *(float4*)(g_qb + (size_t)i * 8)     = make_float4(b[0], b[1], b[2], b[3]);
    *(float4*)(g_qb + (size_t)i * 8 + 4) = make_float4(b[4], b[5], b[6], b[7]);
    *(float4*)(g_qr + (size_t)i * 8)     = make_float4(r[0], r[1], r[2], r[3]);
    *(float4*)(g_qr + (size_t)i * 8 + 4) = make_float4(r[4], r[5], r[6], r[7]);
}

// ---------------- K1: L2 normalize + plain split (for k_logits) ----------------
__global__ void k_normalize(const float* __restrict__ p1, const float* __restrict__ p2) {
    int gw   = (blockIdx.x * blockDim.x + threadIdx.x) >> 5;
    int lane = threadIdx.x & 31;
    if (gw >= 2 * BSZ) return;
    int input = gw >> 12;
    int row   = gw & (BSZ - 1);
    const float* src = (input ? p2 : p1) + (size_t)row * DIM;
    float4 v = ((const float4*)src)[lane];
    float s = v.x * v.x + v.y * v.y + v.z * v.z + v.w * v.w;
#pragma unroll
    for (int o = 16; o; o >>= 1) s += __shfl_xor_sync(0xffffffff, s, o);
    float inv = rsqrtf(s);
    float4 o4 = make_float4(v.x * inv, v.y * inv, v.z * inv, v.w * inv);
    ((float4*)(g_pn[input] + (size_t)row * DIM))[lane] = o4;
    float4 bg, rr;
    bg.x = __uint_as_float(to_tf32_rna(o4.x)); rr.x = o4.x - bg.x;
    bg.y = __uint_as_float(to_tf32_rna(o4.y)); rr.y = o4.y - bg.y;
    bg.z = __uint_as_float(to_tf32_rna(o4.z)); rr.z = o4.z - bg.z;
    bg.w = __uint_as_float(to_tf32_rna(o4.w)); rr.w = o4.w - bg.w;
    ((float4*)(g_pnb[input] + (size_t)row * DIM))[lane] = bg;
    ((float4*)(g_pnr[input] + (size_t)row * DIM))[lane] = rr;
}

// ---------------- K2: 3xTF32 mma GEMM + running argmax (LDS.64 engine) ----------------
// grid (32, 2, 2), block 128 (4 warps as 2 wm x 2 wn), warp tile 64x64.
// BM=128, BN=128, BK=32. A pre-split+permuted in smem (stride 136, FULL k=128).
// B: permuted g_qb/g_qr via cp.async, double-buffered [128][40] arrays (chunk-local k).
#define AST      136
#define BST      40
#define A_ARR    (128 * AST)                   // 17408 floats per array
#define BBUFN    (128 * BST)                   // 5120 floats per array
#define BPAIR    (2 * BBUFN)                   // big+res one buffer
#define NN_SMEM_FLOATS (2 * A_ARR + 2 * BPAIR + 256 + 256)
#define NN_SMEM_BYTES  (NN_SMEM_FLOATS * 4)    // 223,232 B

__global__ void __launch_bounds__(128, 1) k_nn() {
    extern __shared__ float sm[];
    float* Ab    = sm;                          // [128][136] big, permuted
    float* Ar    = sm + A_ARR;                  // [128][136] res, permuted
    float* Bbase = sm + 2 * A_ARR;              // buf j: big @ j*BPAIR, res @ +BBUFN
    float* sval  = Bbase + 2 * BPAIR;           // [128][2]
    int*   sidx  = (int*)(sval + 256);          // [128][2]
    uint32_t sb_B = smem_u32(Bbase);

    const int rb = blockIdx.x, input = blockIdx.y, qseg = blockIdx.z;
    const int tid = threadIdx.x, lane = tid & 31, wid = tid >> 5;
    const int wm = wid & 1, wn = wid >> 1;      // 2 x 2 warp grid
    const int gId = lane >> 2, tig = lane & 3;
    const size_t qbase = (size_t)qseg * QPART * DIM;

    const int NCH = (QPART / 128) * 4;          // 512 chunks (qt 128 x kk 4)

#define NN_COPY(c)                                                              \
    {                                                                           \
        int _qt = (c) >> 2, _kl = ((c) & 3) * 32;                               \
        uint32_t _base = sb_B + (uint32_t)(((c) & 1) * BPAIR) * 4;              \
        _Pragma("unroll")                                                       \
        for (int _x = 0; _x < 16; _x++) {                                       \
            int _f = tid + _x * 128;                                            \
            int _arr = _f >> 10, _rem = _f & 1023;                              \
            int _r = _rem >> 3, _q = _rem & 7;                                  \
            const float* _sp = (_arr ? g_qr : g_qb) + qbase                     \
                + (size_t)(_qt * 128 + _r) * DIM + _kl + _q * 4;                \
            uint32_t _dst = _base + (uint32_t)(_arr * BBUFN + _r * BST + _q * 4) * 4; \
            cp16(_dst, _sp);                                                    \
        }                                                                       \
    }

    // kick off first B chunk before A build (independent smem regions)
    NN_COPY(0);
    CP_COMMIT();

    // ---- build pre-split, pair-permuted A in smem: one row per thread ----
    {
        const float* arow = g_pn[input] + ((size_t)rb * 128 + tid) * DIM;
        float* abr = Ab + tid * AST;
        float* arr_ = Ar + tid * AST;
#pragma unroll
        for (int g = 0; g < 16; g++) {
            float4 lo = *(const float4*)(arow + g * 8);
            float4 hi = *(const float4*)(arow + g * 8 + 4);
            float p[8] = { lo.x, hi.x, lo.y, hi.y, lo.z, hi.z, lo.w, hi.w };
            float b[8], r[8];
#pragma unroll
            for (int t = 0; t < 8; t++) {
                b[t] = __uint_as_float(to_tf32_rna(p[t]));
                r[t] = p[t] - b[t];
            }
            *(float4*)(abr + g * 8)      = make_float4(b[0], b[1], b[2], b[3]);
            *(float4*)(abr + g * 8 + 4)  = make_float4(b[4], b[5], b[6], b[7]);
            *(float4*)(arr_ + g * 8)     = make_float4(r[0], r[1], r[2], r[3]);
            *(float4*)(arr_ + g * 8 + 4) = make_float4(r[4], r[5], r[6], r[7]);
        }
    }

    float best[8]; int bidx[8];
#pragma unroll
    for (int s = 0; s < 8; s++) { best[s] = -3.4e38f; bidx[s] = 0; }

#pragma unroll 1
    for (int qt = 0; qt < QPART / 128; qt++) {
        float c[4][8][4];
#pragma unroll
        for (int ma = 0; ma < 4; ma++)
#pragma unroll
            for (int na = 0; na < 8; na++)
#pragma unroll
                for (int r = 0; r < 4; r++) c[ma][na][r] = 0.f;

#pragma unroll 1
        for (int kk = 0; kk < 4; kk++) {
            int ch = qt * 4 + kk;
            if (ch + 1 < NCH) { NN_COPY(ch + 1); CP_COMMIT(); CP_WAIT(1); }
            else              { CP_WAIT(0); }
            __syncthreads();

            const float* bb = Bbase + (ch & 1) * BPAIR;
            const float* br = bb + BBUFN;
#pragma unroll
            for (int ka = 0; ka < 4; ka++) {
                int kc  = ka * 8 + 2 * tig;        // chunk-local (B smem)
                int kcA = kk * 32 + kc;            // FULL k offset (A smem) — the R11 fix
                uint32_t afb[4][4], afr[4][4], bfb[8][2], bfr[8][2];
#pragma unroll
                for (int ma = 0; ma < 4; ma++) {
                    int rowA = wm * 64 + ma * 16 + gId;
                    float2 p0 = *(const float2*)(Ab + rowA * AST + kcA);
                    float2 p1 = *(const float2*)(Ab + (rowA + 8) * AST + kcA);
                    afb[ma][0] = __float_as_uint(p0.x); afb[ma][1] = __float_as_uint(p1.x);
                    afb[ma][2] = __float_as_uint(p0.y); afb[ma][3] = __float_as_uint(p1.y);
                    float2 q0 = *(const float2*)(Ar + rowA * AST + kcA);
                    float2 q1 = *(const float2*)(Ar + (rowA + 8) * AST + kcA);
                    afr[ma][0] = __float_as_uint(q0.x); afr[ma][1] = __float_as_uint(q1.x);
                    afr[ma][2] = __float_as_uint(q0.y); afr[ma][3] = __float_as_uint(q1.y);
                }
#pragma unroll
                for (int na = 0; na < 8; na++) {
                    int rowB = wn * 64 + na * 8 + gId;
                    float2 pb = *(const float2*)(bb + rowB * BST + kc);
                    bfb[na][0] = __float_as_uint(pb.x); bfb[na][1] = __float_as_uint(pb.y);
                    float2 pr = *(const float2*)(br + rowB * BST + kc);
                    bfr[na][0] = __float_as_uint(pr.x); bfr[na][1] = __float_as_uint(pr.y);
                }
#pragma unroll
                for (int ma = 0; ma < 4; ma++)
#pragma unroll
                    for (int na = 0; na < 8; na++)
                        mma_tf32(c[ma][na], afb[ma], bfb[na]);
#pragma unroll
                for (int ma = 0; ma < 4; ma++)
#pragma unroll
                    for (int na = 0; na < 8; na++)
                        mma_tf32(c[ma][na], afb[ma], bfr[na]);
#pragma unroll
                for (int ma = 0; ma < 4; ma++)
#pragma unroll
                    for (int na = 0; na < 8; na++)
                        mma_tf32(c[ma][na], afr[ma], bfb[na]);
            }
            __syncthreads();
        }

        // fold this 128-col tile into running argmax
        int colb = qseg * QPART + qt * 128 + wn * 64;
#pragma unroll
        for (int ma = 0; ma < 4; ma++) {
#pragma unroll
            for (int na = 0; na < 8; na++) {
                int cb = colb + na * 8 + 2 * tig;
#pragma unroll
                for (int r = 0; r < 4; r++) {
                    int slot = ma * 2 + (r >> 1);
                    float v = c[ma][na][r];
                    if (v > best[slot]) { best[slot] = v; bidx[slot] = cb + (r & 1); }
                }
            }
        }
    }

    // reduce across tig lanes, then across the 2 column-warps
    __syncthreads();
#pragma unroll
    for (int s = 0; s < 8; s++) {
        float v = best[s]; int ix = bidx[s];
#pragma unroll
        for (int off = 1; off <= 2; off <<= 1) {
            float ov = __shfl_xor_sync(0xffffffff, v, off);
            int   oi = __shfl_xor_sync(0xffffffff, ix, off);
            if (ov > v || (ov == v && oi < ix)) { v = ov; ix = oi; }
        }
        if (tig == 0) {
            int row = wm * 64 + (s >> 1) * 16 + gId + ((s & 1) ? 8 : 0);
            sval[row * 2 + wn] = v;
            sidx[row * 2 + wn] = ix;
        }
    }
    __syncthreads();
    {
        float bv = sval[tid * 2]; int bi = sidx[tid * 2];
        float v2 = sval[tid * 2 + 1]; int i2 = sidx[tid * 2 + 1];
        if (v2 > bv || (v2 == bv && i2 < bi)) { bv = v2; bi = i2; }
        g_pval[input][qseg][rb * 128 + tid] = bv;
        g_pidx[input][qseg][rb * 128 + tid] = bi;
    }
}

// ---------------- K3: EXACT fp32 rescore of segment candidates + gather ----------------
__global__ void k_gather(const float* __restrict__ queue) {
    int gw   = (blockIdx.x * blockDim.x + threadIdx.x) >> 5;
    int lane = threadIdx.x & 31;
    if (gw >= 2 * BSZ) return;
    int input = gw >> 12, row = gw & (BSZ - 1);
    float4 p = ((const float4*)(g_pn[input] + (size_t)row * DIM))[lane];
    float bv = -3.4e38f; int bi = 0x7fffffff;
#pragma unroll
    for (int s = 0; s < QSPLIT; s++) {
        int idx = g_pidx[input][s][row];
        float4 q = ((const float4*)(queue + (size_t)idx * DIM))[lane];
        float d = p.x * q.x + p.y * q.y + p.z * q.z + p.w * q.w;
#pragma unroll
        for (int o = 16; o; o >>= 1) d += __shfl_xor_sync(0xffffffff, d, o);
        if (d > bv || (d == bv && idx < bi)) { bv = d; bi = idx; }
    }
    float4 q = ((const float4*)(queue + (size_t)bi * DIM))[lane];
    ((float4*)(g_nn[input] + (size_t)row * DIM))[lane] = q;
}

// ---------------- mma.sync engine macros for k_logits (plain pre-split B) ----------------
#define ASTRIDE 132
#define A_FLOATS (128 * ASTRIDE)
#define BSTRIDE 36
#define BBUF_FLOATS (64 * BSTRIDE)
#define BREGION_FLOATS (4 * BBUF_FLOATS)

#define LOADB2(Bb, Br, rowbase, ch, pvb, pvr)                                     \
    {                                                                             \
        int _qtn = (rowbase) + ((ch) >> 2) * 64, _kkn = ((ch) & 3) * 32;          \
        _Pragma("unroll")                                                         \
        for (int _x = 0; _x < 2; _x++) {                                          \
            int _f = tid + _x * 256, _row = _f >> 3, _kq = _f & 7;                \
            size_t _o = (size_t)(_qtn + _row) * DIM + _kkn + _kq * 4;             \
            pvb[_x] = *(const float4*)((Bb) + _o);                                \
            pvr[_x] = *(const float4*)((Br) + _o);                                \
        }                                                                         \
    }

#define STOREB2(Bbase, ch, pvb, pvr)                                              \
    {                                                                             \
        float* _bb = (Bbase) + ((ch) & 1) * (2 * BBUF_FLOATS);                    \
        float* _br = _bb + BBUF_FLOATS;                                           \
        _Pragma("unroll")                                                         \
        for (int _x = 0; _x < 2; _x++) {                                          \
            int _f = tid + _x * 256, _row = _f >> 3, _kq = _f & 7;                \
            *(float4*)(_bb + _row * BSTRIDE + _kq * 4) = pvb[_x];                 \
            *(float4*)(_br + _row * BSTRIDE + _kq * 4) = pvr[_x];                 \
        }                                                                         \
    }

#define MMA_CHUNK2(As, Bbase, ch, c)                                              \
    {                                                                             \
        float* _bb = (Bbase) + ((ch) & 1) * (2 * BBUF_FLOATS);                    \
        float* _br = _bb + BBUF_FLOATS;                                           \
        int _kkb = ((ch) & 3) * 32;                                               \
        _Pragma("unroll")                                                         \
        for (int _ka = 0; _ka < 4; _ka++) {                                       \
            int _k0 = _kkb + _ka * 8;                                             \
            uint32_t _afb[2][4], _afr[2][4], _bfb[4][2], _bfr[4][2];              \
            _Pragma("unroll")                                                     \
            for (int _ma = 0; _ma < 2; _ma++) {                                   \
                int _r0 = wm * 32 + _ma * 16;                                     \
                _Pragma("unroll")                                                 \
                for (int _q = 0; _q < 4; _q++) {                                  \
                    int _rr2 = _r0 + gId + ((_q & 1) ? 8 : 0);                    \
                    int _ck = _k0 + tig + ((_q & 2) ? 4 : 0);                     \
                    float _a = (As)[_rr2 * ASTRIDE + _ck];                        \
                    uint32_t _big = to_tf32_rna(_a);                              \
                    _afb[_ma][_q] = _big;                                         \
                    _afr[_ma][_q] = __float_as_uint(_a - __uint_as_float(_big));  \
                }                                                                 \
            }                                                                     \
            _Pragma("unroll")                                                     \
            for (int _na = 0; _na < 4; _na++) {                                   \
                int _base = (wn * 32 + _na * 8 + gId) * BSTRIDE + (_k0 - _kkb) + tig; \
                _bfb[_na][0] = __float_as_uint(_bb[_base]);                       \
                _bfb[_na][1] = __float_as_uint(_bb[_base + 4]);                   \
                _bfr[_na][0] = __float_as_uint(_br[_base]);                       \
                _bfr[_na][1] = __float_as_uint(_br[_base + 4]);                   \
            }                                                                     \
            _Pragma("unroll")                                                     \
            for (int _ma = 0; _ma < 2; _ma++)                                     \
                _Pragma("unroll")                                                 \
                for (int _na = 0; _na < 4; _na++)                                 \
                    mma_tf32(c[_ma][_na], _afb[_ma], _bfb[_na]);                  \
            _Pragma("unroll")                                                     \
            for (int _ma = 0; _ma < 2; _ma++)                                     \
                _Pragma("unroll")                                                 \
                for (int _na = 0; _na < 4; _na++)                                 \
                    mma_tf32(c[_ma][_na], _afb[_ma], _bfr[_na]);                  \
            _Pragma("unroll")                                                     \
            for (int _ma = 0; _ma < 2; _ma++)                                     \
                _Pragma("unroll")                                                 \
                for (int _na = 0; _na < 4; _na++)                                 \
                    mma_tf32(c[_ma][_na], _afr[_ma], _bfb[_na]);                  \
        }                                                                         \
    }

// ---------------- K4: logits via mma.sync 3xTF32 + fixed-shift exp partial sums ----------------
#define LG_SMEM_BYTES ((A_FLOATS + BREGION_FLOATS + 64 + 256) * 4)

__global__ void __launch_bounds__(256, 2) k_logits() {
    extern __shared__ float smL[];
    float* As    = smL;
    float* Bbase = smL + A_FLOATS;
    float* scol  = Bbase + BREGION_FLOATS;     // [64]
    float* srow  = scol + 64;                  // [128][2]

    const int rb = blockIdx.x, m = blockIdx.y, nseg = blockIdx.z;
    const float* A  = g_nn[m] + (size_t)rb * 128 * DIM;
    const float* Bb = g_pnb[1 - m];
    const float* Br = g_pnr[1 - m];
    const int rowbase = nseg * NSEG_COLS;
    const int tid = threadIdx.x, lane = tid & 31, wid = tid >> 5;
    const int wm = wid & 3, wn = wid >> 2;
    const int gId = lane >> 2, tig = lane & 3;

#pragma unroll
    for (int x = 0; x < 16; x++) {
        int f = tid + x * 256;
        int row = f >> 5, kq = f & 31;
        float4 v = *(const float4*)(A + (size_t)row * DIM + kq * 4);
        *(float4*)(As + row * ASTRIDE + kq * 4) = v;
    }
    if (tid < 64) scol[tid] = 0.f;

    float rs[4];
#pragma unroll
    for (int s = 0; s < 4; s++) rs[s] = 0.f;

    const int LNCH = (NSEG_COLS / 64) * 4;     // 64 chunks
    float4 pvb[2], pvr[2];
    LOADB2(Bb, Br, rowbase, 0, pvb, pvr);
    STOREB2(Bbase, 0, pvb, pvr);
    __syncthreads();

#pragma unroll 1
    for (int nt = 0; nt < NSEG_COLS / 64; nt++) {
        float c[2][4][4];
#pragma unroll
        for (int ma = 0; ma < 2; ma++)
#pragma unroll
            for (int na = 0; na < 4; na++)
#pragma unroll
                for (int r = 0; r < 4; r++) c[ma][na][r] = 0.f;

#pragma unroll 1
        for (int kk = 0; kk < 4; kk++) {
            int ch = nt * 4 + kk;
            if (ch + 1 < LNCH) LOADB2(Bb, Br, rowbase, ch + 1, pvb, pvr);
            MMA_CHUNK2(As, Bbase, ch, c);
            if (ch + 1 < LNCH) STOREB2(Bbase, ch + 1, pvb, pvr);
            __syncthreads();
        }

        float ctmp[4][2];
#pragma unroll
        for (int na = 0; na < 4; na++) { ctmp[na][0] = 0.f; ctmp[na][1] = 0.f; }
        int gcol0 = rowbase + nt * 64 + wn * 32;
#pragma unroll
        for (int ma = 0; ma < 2; ma++) {
#pragma unroll
            for (int na = 0; na < 4; na++) {
#pragma unroll
                for (int r = 0; r < 4; r++) {
                    float l = c[ma][na][r] * INV_T;
                    float e = __expf(l - SHIFT);
                    int half = r >> 1;
                    rs[ma * 2 + half] += e;
                    ctmp[na][r & 1] += e;
                    int grow = rb * 128 + wm * 32 + ma * 16 + gId + half * 8;
                    int gcol = gcol0 + na * 8 + 2 * tig + (r & 1);
                    if (gcol == grow) g_diag[m][grow] = l;
                }
            }
        }
#pragma unroll
        for (int na = 0; na < 4; na++)
#pragma unroll
            for (int r = 0; r < 2; r++) {
#pragma unroll
                for (int off = 4; off <= 16; off <<= 1)
                    ctmp[na][r] += __shfl_xor_sync(0xffffffff, ctmp[na][r], off);
            }
        if (gId == 0) {
#pragma unroll
            for (int na = 0; na < 4; na++) {
                atomicAdd(&scol[wn * 32 + na * 8 + 2 * tig + 0], ctmp[na][0]);
                atomicAdd(&scol[wn * 32 + na * 8 + 2 * tig + 1], ctmp[na][1]);
            }
        }
        __syncthreads();
        if (tid < 64) {
            g_colpart[m][rb][rowbase + nt * 64 + tid] = scol[tid];
            scol[tid] = 0.f;
        }
    }

#pragma unroll
    for (int s = 0; s < 4; s++) {
#pragma unroll
        for (int off = 1; off <= 2; off <<= 1)
            rs[s] += __shfl_xor_sync(0xffffffff, rs[s], off);
        if (tig == 0) {
            int rloc = wm * 32 + (s >> 1) * 16 + gId + ((s & 1) ? 8 : 0);
            srow[rloc * 2 + wn] = rs[s];
        }
    }
    __syncthreads();
    if (tid < 128)
        g_rowpart[m][nseg][rb * 128 + tid] = srow[tid * 2] + srow[tid * 2 + 1];
}

// ---------------- K5: final losses from partials ----------------
__global__ void k_loss(float* __restrict__ out) {
    int g = blockIdx.x * blockDim.x + threadIdx.x;
    if (g >= 2 * BSZ) return;
    int m = g >> 12, i = g & (BSZ - 1);
    float rsum = 0.f, csum = 0.f;
#pragma unroll
    for (int s = 0; s < NSEG; s++) rsum += g_rowpart[m][s][i];
#pragma unroll 8
    for (int rb = 0; rb < 32; rb++) csum += g_colpart[m][rb][i];
    float d = g_diag[m][i];
    out[(size_t)(2 * m) * BSZ + i]     = SHIFT + logf(rsum) - d;
    out[(size_t)(2 * m + 1) * BSZ + i] = SHIFT + logf(csum) - d;
}

// ---------------- launch ----------------
extern "C" void kernel_launch(void* const* d_in, const int* in_sizes, int n_in,
                              void* d_out, int out_size) {
    const float *p1 = nullptr, *p2 = nullptr, *queue = nullptr;
    for (int i = 0; i < n_in; i++) {
        if (in_sizes[i] == QSZ * DIM) queue = (const float*)d_in[i];
        else if (!p1) p1 = (const float*)d_in[i];
        else p2 = (const float*)d_in[i];
    }
    float* out = (float*)d_out;

    cudaFuncSetAttribute(k_nn, cudaFuncAttributeMaxDynamicSharedMemorySize, NN_SMEM_BYTES);
    cudaFuncSetAttribute(k_logits, cudaFuncAttributeMaxDynamicSharedMemorySize, LG_SMEM_BYTES);

    k_normalize<<<(2 * BSZ * 32 + 255) / 256, 256>>>(p1, p2);
    k_qsplit<<<(QSZ * DIM / 8 + 255) / 256, 256>>>(queue);

    dim3 g2(BSZ / 128, 2, QSPLIT);
    k_nn<<<g2, 128, NN_SMEM_BYTES>>>();

    k_gather<<<(2 * BSZ * 32 + 255) / 256, 256>>>(queue);

    dim3 g4(BSZ / 128, 2, NSEG);
    k_logits<<<g4, 256, LG_SMEM_BYTES>>>();

    k_loss<<<(2 * BSZ + 255) / 256, 256>>>(out);
}

// round 13
// speedup vs baseline: 1.9501x; 1.9501x over previous
#include <cuda_runtime.h>
#include <math.h>
#include <stdint.h>

#define BSZ   4096
#define QSZ   32768
#define DIM   128
#define QSPLIT 2
#define QPART (QSZ / QSPLIT)   // 16384
#define NSEG  4
#define NSEG_COLS (BSZ / NSEG) // 1024

#define INV_T 10.0f
#define SHIFT 10.0f

// ---------------- scratch (static device globals; no allocation) ----------------
__device__ float    g_pn [2][BSZ * DIM];
__device__ float    g_pnb[2][BSZ * DIM];     // tf32 split, plain layout (k_logits B)
__device__ float    g_pnr[2][BSZ * DIM];
__device__ float    g_nn [2][BSZ * DIM];
__device__ uint32_t g_qh [QSZ * DIM / 2];    // queue bf16-hi, packed k-pairs (8 MB)
__device__ uint32_t g_qm [QSZ * DIM / 2];    // queue bf16-mid
__device__ float    g_pval[2][QSPLIT][BSZ];
__device__ int      g_pidx[2][QSPLIT][BSZ];
__device__ float    g_rowpart[2][NSEG][BSZ];
__device__ float    g_colpart[2][32][BSZ];
__device__ float    g_diag[2][BSZ];

// ---------------- helpers ----------------
__device__ __forceinline__ uint32_t smem_u32(const void* p) {
    uint32_t a;
    asm("{ .reg .u64 t; cvta.to.shared.u64 t, %1; cvt.u32.u64 %0, t; }" : "=r"(a) : "l"(p));
    return a;
}
__device__ __forceinline__ uint32_t to_tf32_rna(float x) {
    uint32_t r;
    asm("cvt.rna.tf32.f32 %0, %1;" : "=r"(r) : "f"(x));
    return r;
}
__device__ __forceinline__ void mma_tf32(float c[4], const uint32_t a[4], const uint32_t b[2]) {
    asm volatile(
        "mma.sync.aligned.m16n8k8.row.col.f32.tf32.tf32.f32 "
        "{%0,%1,%2,%3}, {%4,%5,%6,%7}, {%8,%9}, {%0,%1,%2,%3};\n"
        : "+f"(c[0]), "+f"(c[1]), "+f"(c[2]), "+f"(c[3])
        : "r"(a[0]), "r"(a[1]), "r"(a[2]), "r"(a[3]), "r"(b[0]), "r"(b[1]));
}
__device__ __forceinline__ void mma_bf16(float c[4], const uint32_t a[4], const uint32_t b[2]) {
    asm volatile(
        "mma.sync.aligned.m16n8k16.row.col.f32.bf16.bf16.f32 "
        "{%0,%1,%2,%3}, {%4,%5,%6,%7}, {%8,%9}, {%0,%1,%2,%3};\n"
        : "+f"(c[0]), "+f"(c[1]), "+f"(c[2]), "+f"(c[3])
        : "r"(a[0]), "r"(a[1]), "r"(a[2]), "r"(a[3]), "r"(b[0]), "r"(b[1]));
}
// pack two floats into bf16x2 word: lo in low half, hi_ in high half
__device__ __forceinline__ uint32_t pack_bf16(float lo, float hi_) {
    uint32_t r;
    asm("cvt.rn.bf16x2.f32 %0, %1, %2;" : "=r"(r) : "f"(hi_), "f"(lo));
    return r;
}
__device__ __forceinline__ void split8_bf16(const float* p, uint32_t oh[4], uint32_t om[4]) {
#pragma unroll
    for (int t = 0; t < 4; t++) {
        float f0 = p[2 * t], f1 = p[2 * t + 1];
        uint32_t h = pack_bf16(f0, f1);
        float h0 = __uint_as_float(h << 16);
        float h1 = __uint_as_float(h & 0xffff0000u);
        oh[t] = h;
        om[t] = pack_bf16(f0 - h0, f1 - h1);
    }
}
__device__ __forceinline__ void cp16(uint32_t dst, const void* src) {
    asm volatile("cp.async.cg.shared.global [%0], [%1], 16;" :: "r"(dst), "l"(src) : "memory");
}
#define CP_COMMIT() asm volatile("cp.async.commit_group;" ::: "memory")
#define CP_WAIT(n)  asm volatile("cp.async.wait_group %0;" :: "n"(n) : "memory")

// ---------------- K0: split queue into bf16 hi/mid (packed k-pairs) ----------------
__global__ void k_qsplit(const float* __restrict__ queue) {
    int i = blockIdx.x * blockDim.x + threadIdx.x;    // one group of 8 floats
    if (i >= QSZ * DIM / 8) return;
    uint32_t oh[4], om[4];
    split8_bf16(queue + (size_t)i * 8, oh, om);
#pragma unroll
    for (int t = 0; t < 4; t++) {
        g_qh[(size_t)i * 4 + t] = oh[t];
        g_qm[(size_t)i * 4 + t] = om[t];
    }
}

// ---------------- K1: L2 normalize + tf32 split (for k_logits) ----------------
__global__ void k_normalize(const float* __restrict__ p1, const float* __restrict__ p2) {
    int gw   = (blockIdx.x * blockDim.x + threadIdx.x) >> 5;
    int lane = threadIdx.x & 31;
    if (gw >= 2 * BSZ) return;
    int input = gw >> 12;
    int row   = gw & (BSZ - 1);
    const float* src = (input ? p2 : p1) + (size_t)row * DIM;
    float4 v = ((const float4*)src)[lane];
    float s = v.x * v.x + v.y * v.y + v.z * v.z + v.w * v.w;
#pragma unroll
    for (int o = 16; o; o >>= 1) s += __shfl_xor_sync(0xffffffff, s, o);
    float inv = rsqrtf(s);
    float4 o4 = make_float4(v.x * inv, v.y * inv, v.z * inv, v.w * inv);
    ((float4*)(g_pn[input] + (size_t)row * DIM))[lane] = o4;
    float4 bg, rr;
    bg.x = __uint_as_float(to_tf32_rna(o4.x)); rr.x = o4.x - bg.x;
    bg.y = __uint_as_float(to_tf32_rna(o4.y)); rr.y = o4.y - bg.y;
    bg.z = __uint_as_float(to_tf32_rna(o4.z)); rr.z = o4.z - bg.z;
    bg.w = __uint_as_float(to_tf32_rna(o4.w)); rr.w = o4.w - bg.w;
    ((float4*)(g_pnb[input] + (size_t)row * DIM))[lane] = bg;
    ((float4*)(g_pnr[input] + (size_t)row * DIM))[lane] = rr;
}

// ---------------- K2: 3-term bf16 m16n8k16 GEMM + running argmax ----------------
// grid (32, 2, 2), block 256 (8 warps: wm = wid&1 (2), wn = wid>>1 (4)).
// BM=128, BN=256, warp tile 64x64. A pre-split bf16 hi/mid in smem (word stride 68).
// B: pre-split g_qh/g_qm via cp.async, double-buffered [256 col][20 words] arrays.
#define A_WST   68                              // words per A row (64 data + 4 pad)
#define B_WST   20                              // words per B col (16 data + 4 pad)
#define A_WORDS (128 * A_WST)                   // 8704 per array
#define B_WORDS (256 * B_WST)                   // 5120 per array
#define BPAIRW  (2 * B_WORDS)                   // hi+mid one buffer
#define NN_SMEM_WORDS (2 * A_WORDS + 2 * BPAIRW + 512 + 512)
#define NN_SMEM_BYTES (NN_SMEM_WORDS * 4)       // 155,648 B

__global__ void __launch_bounds__(256, 1) k_nn() {
    extern __shared__ uint32_t smw[];
    uint32_t* Ah    = smw;                       // [128][68] words
    uint32_t* Am    = smw + A_WORDS;
    uint32_t* Bbase = smw + 2 * A_WORDS;         // buf j @ j*BPAIRW: hi @0, mid @+B_WORDS
    float*    sval  = (float*)(Bbase + 2 * BPAIRW);   // [128][4]
    int*      sidx  = (int*)(sval + 512);             // [128][4]
    uint32_t sb_B = smem_u32(Bbase);

    const int rb = blockIdx.x, input = blockIdx.y, qseg = blockIdx.z;
    const int tid = threadIdx.x, lane = tid & 31, wid = tid >> 5;
    const int wm = wid & 1, wn = wid >> 1;       // 2 x 4 warp grid
    const int gId = lane >> 2, tig = lane & 3;
    const size_t qbaseW = (size_t)qseg * QPART * (DIM / 2);

    const int NCH = (QPART / 256) * 4;           // 256 chunks (qt 64 x kk 4)

    // cp.async copy of chunk c (256 cols x 32 k, hi+mid) into buffer c&1: 8 cp16/thread
#define NN_COPY(c)                                                              \
    {                                                                           \
        int _qt = (c) >> 2, _klw = ((c) & 3) * 16;                              \
        uint32_t _base = sb_B + (uint32_t)(((c) & 1) * BPAIRW) * 4;             \
        _Pragma("unroll")                                                       \
        for (int _x = 0; _x < 8; _x++) {                                        \
            int _f = tid + _x * 256;                                            \
            int _arr = _f >> 10, _rem = _f & 1023;                              \
            int _r = _rem >> 2, _q = _rem & 3;                                  \
            const uint32_t* _sp = (_arr ? g_qm : g_qh) + qbaseW                 \
                + (size_t)(_qt * 256 + _r) * (DIM / 2) + _klw + _q * 4;         \
            uint32_t _dst = _base + (uint32_t)(_arr * B_WORDS + _r * B_WST + _q * 4) * 4; \
            cp16(_dst, _sp);                                                    \
        }                                                                       \
    }

    NN_COPY(0);
    CP_COMMIT();

    // ---- build bf16 hi/mid A in smem: 2 threads per row (half = 64 k each) ----
    {
        int row = tid >> 1, half = tid & 1;
        const float* arow = g_pn[input] + ((size_t)rb * 128 + row) * DIM + half * 64;
        uint32_t wbase = row * A_WST + half * 32;
#pragma unroll
        for (int g = 0; g < 8; g++) {
            uint32_t oh[4], om[4];
            split8_bf16(arow + g * 8, oh, om);
#pragma unroll
            for (int t = 0; t < 4; t++) {
                Ah[wbase + g * 4 + t] = oh[t];
                Am[wbase + g * 4 + t] = om[t];
            }
        }
    }

    float best[8]; int bidx[8];
#pragma unroll
    for (int s = 0; s < 8; s++) { best[s] = -3.4e38f; bidx[s] = 0; }

#pragma unroll 1
    for (int qt = 0; qt < QPART / 256; qt++) {
        float c[4][8][4];
#pragma unroll
        for (int ma = 0; ma < 4; ma++)
#pragma unroll
            for (int na = 0; na < 8; na++)
#pragma unroll
                for (int r = 0; r < 4; r++) c[ma][na][r] = 0.f;

#pragma unroll 1
        for (int kk = 0; kk < 4; kk++) {
            int ch = qt * 4 + kk;
            if (ch + 1 < NCH) { NN_COPY(ch + 1); CP_COMMIT(); CP_WAIT(1); }
            else              { CP_WAIT(0); }
            __syncthreads();

            const uint32_t* bh = Bbase + (ch & 1) * BPAIRW;
            const uint32_t* bm = bh + B_WORDS;
#pragma unroll
            for (int ka = 0; ka < 2; ka++) {
                int kwB = ka * 8 + tig;          // chunk-local word (k16 atom)
                int kwA = kk * 16 + kwB;         // full-k word (A)
                uint32_t ah[4][4], am[4][4], bhf[8][2], bmf[8][2];
#pragma unroll
                for (int ma = 0; ma < 4; ma++) {
                    int rowA = wm * 64 + ma * 16 + gId;
                    ah[ma][0] = Ah[rowA * A_WST + kwA];
                    ah[ma][1] = Ah[(rowA + 8) * A_WST + kwA];
                    ah[ma][2] = Ah[rowA * A_WST + kwA + 4];
                    ah[ma][3] = Ah[(rowA + 8) * A_WST + kwA + 4];
                    am[ma][0] = Am[rowA * A_WST + kwA];
                    am[ma][1] = Am[(rowA + 8) * A_WST + kwA];
                    am[ma][2] = Am[rowA * A_WST + kwA + 4];
                    am[ma][3] = Am[(rowA + 8) * A_WST + kwA + 4];
                }
#pragma unroll
                for (int na = 0; na < 8; na++) {
                    int colB = wn * 64 + na * 8 + gId;
                    bhf[na][0] = bh[colB * B_WST + kwB];
                    bhf[na][1] = bh[colB * B_WST + kwB + 4];
                    bmf[na][0] = bm[colB * B_WST + kwB];
                    bmf[na][1] = bm[colB * B_WST + kwB + 4];
                }
                // hi*hi, hi*mid, mid*hi
#pragma unroll
                for (int ma = 0; ma < 4; ma++)
#pragma unroll
                    for (int na = 0; na < 8; na++)
                        mma_bf16(c[ma][na], ah[ma], bhf[na]);
#pragma unroll
                for (int ma = 0; ma < 4; ma++)
#pragma unroll
                    for (int na = 0; na < 8; na++)
                        mma_bf16(c[ma][na], ah[ma], bmf[na]);
#pragma unroll
                for (int ma = 0; ma < 4; ma++)
#pragma unroll
                    for (int na = 0; na < 8; na++)
                        mma_bf16(c[ma][na], am[ma], bhf[na]);
            }
            __syncthreads();
        }

        // fold this 256-col tile into running argmax
        int colb = qseg * QPART + qt * 256 + wn * 64;
#pragma unroll
        for (int ma = 0; ma < 4; ma++) {
#pragma unroll
            for (int na = 0; na < 8; na++) {
                int cb = colb + na * 8 + 2 * tig;
#pragma unroll
                for (int r = 0; r < 4; r++) {
                    int slot = ma * 2 + (r >> 1);
                    float v = c[ma][na][r];
                    if (v > best[slot]) { best[slot] = v; bidx[slot] = cb + (r & 1); }
                }
            }
        }
    }

    // reduce across tig lanes, then across the 4 column-warps
    __syncthreads();
#pragma unroll
    for (int s = 0; s < 8; s++) {
        float v = best[s]; int ix = bidx[s];
#pragma unroll
        for (int off = 1; off <= 2; off <<= 1) {
            float ov = __shfl_xor_sync(0xffffffff, v, off);
            int   oi = __shfl_xor_sync(0xffffffff, ix, off);
            if (ov > v || (ov == v && oi < ix)) { v = ov; ix = oi; }
        }
        if (tig == 0) {
            int row = wm * 64 + (s >> 1) * 16 + gId + ((s & 1) ? 8 : 0);
            sval[row * 4 + wn] = v;
            sidx[row * 4 + wn] = ix;
        }
    }
    __syncthreads();
    if (tid < 128) {
        float bv = -3.4e38f; int bi = 0x7fffffff;
#pragma unroll
        for (int w = 0; w < 4; w++) {
            float v = sval[tid * 4 + w]; int ix = sidx[tid * 4 + w];
            if (v > bv || (v == bv && ix < bi)) { bv = v; bi = ix; }
        }
        g_pval[input][qseg][rb * 128 + tid] = bv;
        g_pidx[input][qseg][rb * 128 + tid] = bi;
    }
}

// ---------------- K3: EXACT fp32 rescore of segment candidates + gather ----------------
__global__ void k_gather(const float* __restrict__ queue) {
    int gw   = (blockIdx.x * blockDim.x + threadIdx.x) >> 5;
    int lane = threadIdx.x & 31;
    if (gw >= 2 * BSZ) return;
    int input = gw >> 12, row = gw & (BSZ - 1);
    float4 p = ((const float4*)(g_pn[input] + (size_t)row * DIM))[lane];
    float bv = -3.4e38f; int bi = 0x7fffffff;
#pragma unroll
    for (int s = 0; s < QSPLIT; s++) {
        int idx = g_pidx[input][s][row];
        float4 q = ((const float4*)(queue + (size_t)idx * DIM))[lane];
        float d = p.x * q.x + p.y * q.y + p.z * q.z + p.w * q.w;
#pragma unroll
        for (int o = 16; o; o >>= 1) d += __shfl_xor_sync(0xffffffff, d, o);
        if (d > bv || (d == bv && idx < bi)) { bv = d; bi = idx; }
    }
    float4 q = ((const float4*)(queue + (size_t)bi * DIM))[lane];
    ((float4*)(g_nn[input] + (size_t)row * DIM))[lane] = q;
}

// ---------------- mma.sync tf32 engine macros for k_logits (plain pre-split B) ----------------
#define ASTRIDE 132
#define A_FLOATS (128 * ASTRIDE)
#define BSTRIDE 36
#define BBUF_FLOATS (64 * BSTRIDE)
#define BREGION_FLOATS (4 * BBUF_FLOATS)

#define LOADB2(Bb, Br, rowbase, ch, pvb, pvr)                                     \
    {                                                                             \
        int _qtn = (rowbase) + ((ch) >> 2) * 64, _kkn = ((ch) & 3) * 32;          \
        _Pragma("unroll")                                                         \
        for (int _x = 0; _x < 2; _x++) {                                          \
            int _f = tid + _x * 256, _row = _f >> 3, _kq = _f & 7;                \
            size_t _o = (size_t)(_qtn + _row) * DIM + _kkn + _kq * 4;             \
            pvb[_x] = *(const float4*)((Bb) + _o);                                \
            pvr[_x] = *(const float4*)((Br) + _o);                                \
        }                                                                         \
    }

#define STOREB2(Bbase, ch, pvb, pvr)                                              \
    {                                                                             \
        float* _bb = (Bbase) + ((ch) & 1) * (2 * BBUF_FLOATS);                    \
        float* _br = _bb + BBUF_FLOATS;                                           \
        _Pragma("unroll")                                                         \
        for (int _x = 0; _x < 2; _x++) {                                          \
            int _f = tid + _x * 256, _row = _f >> 3, _kq = _f & 7;                \
            *(float4*)(_bb + _row * BSTRIDE + _kq * 4) = pvb[_x];                 \
            *(float4*)(_br + _row * BSTRIDE + _kq * 4) = pvr[_x];                 \
        }                                                                         \
    }

#define MMA_CHUNK2(As, Bbase, ch, c)                                              \
    {                                                                             \
        float* _bb = (Bbase) + ((ch) & 1) * (2 * BBUF_FLOATS);                    \
        float* _br = _bb + BBUF_FLOATS;                                           \
        int _kkb = ((ch) & 3) * 32;                                               \
        _Pragma("unroll")                                                         \
        for (int _ka = 0; _ka < 4; _ka++) {                                       \
            int _k0 = _kkb + _ka * 8;                                             \
            uint32_t _afb[2][4], _afr[2][4], _bfb[4][2], _bfr[4][2];              \
            _Pragma("unroll")                                                     \
            for (int _ma = 0; _ma < 2; _ma++) {                                   \
                int _r0 = wm * 32 + _ma * 16;                                     \
                _Pragma("unroll")                                                 \
                for (int _q = 0; _q < 4; _q++) {                                  \
                    int _rr2 = _r0 + gId + ((_q & 1) ? 8 : 0);                    \
                    int _ck = _k0 + tig + ((_q & 2) ? 4 : 0);                     \
                    float _a = (As)[_rr2 * ASTRIDE + _ck];                        \
                    uint32_t _big = to_tf32_rna(_a);                              \
                    _afb[_ma][_q] = _big;                                         \
                    _afr[_ma][_q] = __float_as_uint(_a - __uint_as_float(_big));  \
                }                                                                 \
            }                                                                     \
            _Pragma("unroll")                                                     \
            for (int _na = 0; _na < 4; _na++) {                                   \
                int _base = (wn * 32 + _na * 8 + gId) * BSTRIDE + (_k0 - _kkb) + tig; \
                _bfb[_na][0] = __float_as_uint(_bb[_base]);                       \
                _bfb[_na][1] = __float_as_uint(_bb[_base + 4]);                   \
                _bfr[_na][0] = __float_as_uint(_br[_base]);                       \
                _bfr[_na][1] = __float_as_uint(_br[_base + 4]);                   \
            }                                                                     \
            _Pragma("unroll")                                                     \
            for (int _ma = 0; _ma < 2; _ma++)                                     \
                _Pragma("unroll")                                                 \
                for (int _na = 0; _na < 4; _na++)                                 \
                    mma_tf32(c[_ma][_na], _afb[_ma], _bfb[_na]);                  \
            _Pragma("unroll")                                                     \
            for (int _ma = 0; _ma < 2; _ma++)                                     \
                _Pragma("unroll")                                                 \
                for (int _na = 0; _na < 4; _na++)                                 \
                    mma_tf32(c[_ma][_na], _afb[_ma], _bfr[_na]);                  \
            _Pragma("unroll")                                                     \
            for (int _ma = 0; _ma < 2; _ma++)                                     \
                _Pragma("unroll")                                                 \
                for (int _na = 0; _na < 4; _na++)                                 \
                    mma_tf32(c[_ma][_na], _afr[_ma], _bfb[_na]);                  \
        }                                                                         \
    }

// ---------------- K4: logits via mma.sync 3xTF32 + fixed-shift exp partial sums ----------------
#define LG_SMEM_BYTES ((A_FLOATS + BREGION_FLOATS + 64 + 256) * 4)

__global__ void __launch_bounds__(256, 2) k_logits() {
    extern __shared__ float smL[];
    float* As    = smL;
    float* Bbase = smL + A_FLOATS;
    float* scol  = Bbase + BREGION_FLOATS;     // [64]
    float* srow  = scol + 64;                  // [128][2]

    const int rb = blockIdx.x, m = blockIdx.y, nseg = blockIdx.z;
    const float* A  = g_nn[m] + (size_t)rb * 128 * DIM;
    const float* Bb = g_pnb[1 - m];
    const float* Br = g_pnr[1 - m];
    const int rowbase = nseg * NSEG_COLS;
    const int tid = threadIdx.x, lane = tid & 31, wid = tid >> 5;
    const int wm = wid & 3, wn = wid >> 2;
    const int gId = lane >> 2, tig = lane & 3;

#pragma unroll
    for (int x = 0; x < 16; x++) {
        int f = tid + x * 256;
        int row = f >> 5, kq = f & 31;
        float4 v = *(const float4*)(A + (size_t)row * DIM + kq * 4);
        *(float4*)(As + row * ASTRIDE + kq * 4) = v;
    }
    if (tid < 64) scol[tid] = 0.f;

    float rs[4];
#pragma unroll
    for (int s = 0; s < 4; s++) rs[s] = 0.f;

    const int LNCH = (NSEG_COLS / 64) * 4;     // 64 chunks
    float4 pvb[2], pvr[2];
    LOADB2(Bb, Br, rowbase, 0, pvb, pvr);
    STOREB2(Bbase, 0, pvb, pvr);
    __syncthreads();

#pragma unroll 1
    for (int nt = 0; nt < NSEG_COLS / 64; nt++) {
        float c[2][4][4];
#pragma unroll
        for (int ma = 0; ma < 2; ma++)
#pragma unroll
            for (int na = 0; na < 4; na++)
#pragma unroll
                for (int r = 0; r < 4; r++) c[ma][na][r] = 0.f;

#pragma unroll 1
        for (int kk = 0; kk < 4; kk++) {
            int ch = nt * 4 + kk;
            if (ch + 1 < LNCH) LOADB2(Bb, Br, rowbase, ch + 1, pvb, pvr);
            MMA_CHUNK2(As, Bbase, ch, c);
            if (ch + 1 < LNCH) STOREB2(Bbase, ch + 1, pvb, pvr);
            __syncthreads();
        }

        float ctmp[4][2];
#pragma unroll
        for (int na = 0; na < 4; na++) { ctmp[na][0] = 0.f; ctmp[na][1] = 0.f; }
        int gcol0 = rowbase + nt * 64 + wn * 32;
#pragma unroll
        for (int ma = 0; ma < 2; ma++) {
#pragma unroll
            for (int na = 0; na < 4; na++) {
#pragma unroll
                for (int r = 0; r < 4; r++) {
                    float l = c[ma][na][r] * INV_T;
                    float e = __expf(l - SHIFT);
                    int half = r >> 1;
                    rs[ma * 2 + half] += e;
                    ctmp[na][r & 1] += e;
                    int grow = rb * 128 + wm * 32 + ma * 16 + gId + half * 8;
                    int gcol = gcol0 + na * 8 + 2 * tig + (r & 1);
                    if (gcol == grow) g_diag[m][grow] = l;
                }
            }
        }
#pragma unroll
        for (int na = 0; na < 4; na++)
#pragma unroll
            for (int r = 0; r < 2; r++) {
#pragma unroll
                for (int off = 4; off <= 16; off <<= 1)
                    ctmp[na][r] += __shfl_xor_sync(0xffffffff, ctmp[na][r], off);
            }
        if (gId == 0) {
#pragma unroll
            for (int na = 0; na < 4; na++) {
                atomicAdd(&scol[wn * 32 + na * 8 + 2 * tig + 0], ctmp[na][0]);
                atomicAdd(&scol[wn * 32 + na * 8 + 2 * tig + 1], ctmp[na][1]);
            }
        }
        __syncthreads();
        if (tid < 64) {
            g_colpart[m][rb][rowbase + nt * 64 + tid] = scol[tid];
            scol[tid] = 0.f;
        }
    }

#pragma unroll
    for (int s = 0; s < 4; s++) {
#pragma unroll
        for (int off = 1; off <= 2; off <<= 1)
            rs[s] += __shfl_xor_sync(0xffffffff, rs[s], off);
        if (tig == 0) {
            int rloc = wm * 32 + (s >> 1) * 16 + gId + ((s & 1) ? 8 : 0);
            srow[rloc * 2 + wn] = rs[s];
        }
    }
    __syncthreads();
    if (tid < 128)
        g_rowpart[m][nseg][rb * 128 + tid] = srow[tid * 2] + srow[tid * 2 + 1];
}

// ---------------- K5: final losses from partials ----------------
__global__ void k_loss(float* __restrict__ out) {
    int g = blockIdx.x * blockDim.x + threadIdx.x;
    if (g >= 2 * BSZ) return;
    int m = g >> 12, i = g & (BSZ - 1);
    float rsum = 0.f, csum = 0.f;
#pragma unroll
    for (int s = 0; s < NSEG; s++) rsum += g_rowpart[m][s][i];
#pragma unroll 8
    for (int rb = 0; rb < 32; rb++) csum += g_colpart[m][rb][i];
    float d = g_diag[m][i];
    out[(size_t)(2 * m) * BSZ + i]     = SHIFT + logf(rsum) - d;
    out[(size_t)(2 * m + 1) * BSZ + i] = SHIFT + logf(csum) - d;
}

// ---------------- launch ----------------
extern "C" void kernel_launch(void* const* d_in, const int* in_sizes, int n_in,
                              void* d_out, int out_size) {
    const float *p1 = nullptr, *p2 = nullptr, *queue = nullptr;
    for (int i = 0; i < n_in; i++) {
        if (in_sizes[i] == QSZ * DIM) queue = (const float*)d_in[i];
        else if (!p1) p1 = (const float*)d_in[i];
        else p2 = (const float*)d_in[i];
    }
    float* out = (float*)d_out;

    cudaFuncSetAttribute(k_nn, cudaFuncAttributeMaxDynamicSharedMemorySize, NN_SMEM_BYTES);
    cudaFuncSetAttribute(k_logits, cudaFuncAttributeMaxDynamicSharedMemorySize, LG_SMEM_BYTES);

    k_normalize<<<(2 * BSZ * 32 + 255) / 256, 256>>>(p1, p2);
    k_qsplit<<<(QSZ * DIM / 8 + 255) / 256, 256>>>(queue);

    dim3 g2(BSZ / 128, 2, QSPLIT);
    k_nn<<<g2, 256, NN_SMEM_BYTES>>>();

    k_gather<<<(2 * BSZ * 32 + 255) / 256, 256>>>(queue);

    dim3 g4(BSZ / 128, 2, NSEG);
    k_logits<<<g4, 256, LG_SMEM_BYTES>>>();

    k_loss<<<(2 * BSZ + 255) / 256, 256>>>(out);
}

// round 14
// speedup vs baseline: 2.1030x; 1.0784x over previous
#include <cuda_runtime.h>
#include <math.h>
#include <stdint.h>

#define BSZ   4096
#define QSZ   32768
#define DIM   128
#define QSPLIT 2
#define QPART (QSZ / QSPLIT)   // 16384
#define LG_NSEG  2
#define LG_COLS  (BSZ / LG_NSEG) // 2048

#define INV_T 10.0f
#define SHIFT 10.0f

// ---------------- scratch (static device globals; no allocation) ----------------
__device__ float    g_pn [2][BSZ * DIM];
__device__ uint32_t g_pnh[2][BSZ * DIM / 2];  // p normalized, bf16-hi packed pairs
__device__ uint32_t g_pnm[2][BSZ * DIM / 2];  // bf16-mid
__device__ float    g_nn [2][BSZ * DIM];
__device__ uint32_t g_qh [QSZ * DIM / 2];     // queue bf16-hi packed pairs (8 MB)
__device__ uint32_t g_qm [QSZ * DIM / 2];
__device__ float    g_pval[2][QSPLIT][BSZ];
__device__ int      g_pidx[2][QSPLIT][BSZ];
__device__ float    g_rowpart[2][LG_NSEG][BSZ];
__device__ float    g_colpart[2][32][BSZ];
__device__ float    g_diag[2][BSZ];

// ---------------- helpers ----------------
__device__ __forceinline__ uint32_t smem_u32(const void* p) {
    uint32_t a;
    asm("{ .reg .u64 t; cvta.to.shared.u64 t, %1; cvt.u32.u64 %0, t; }" : "=r"(a) : "l"(p));
    return a;
}
__device__ __forceinline__ void mma_bf16(float c[4], const uint32_t a[4], const uint32_t b[2]) {
    asm volatile(
        "mma.sync.aligned.m16n8k16.row.col.f32.bf16.bf16.f32 "
        "{%0,%1,%2,%3}, {%4,%5,%6,%7}, {%8,%9}, {%0,%1,%2,%3};\n"
        : "+f"(c[0]), "+f"(c[1]), "+f"(c[2]), "+f"(c[3])
        : "r"(a[0]), "r"(a[1]), "r"(a[2]), "r"(a[3]), "r"(b[0]), "r"(b[1]));
}
__device__ __forceinline__ uint32_t pack_bf16(float lo, float hi_) {
    uint32_t r;
    asm("cvt.rn.bf16x2.f32 %0, %1, %2;" : "=r"(r) : "f"(hi_), "f"(lo));
    return r;
}
__device__ __forceinline__ void split8_bf16(const float* p, uint32_t oh[4], uint32_t om[4]) {
#pragma unroll
    for (int t = 0; t < 4; t++) {
        float f0 = p[2 * t], f1 = p[2 * t + 1];
        uint32_t h = pack_bf16(f0, f1);
        float h0 = __uint_as_float(h << 16);
        float h1 = __uint_as_float(h & 0xffff0000u);
        oh[t] = h;
        om[t] = pack_bf16(f0 - h0, f1 - h1);
    }
}
__device__ __forceinline__ void cp16(uint32_t dst, const void* src) {
    asm volatile("cp.async.cg.shared.global [%0], [%1], 16;" :: "r"(dst), "l"(src) : "memory");
}
#define CP_COMMIT() asm volatile("cp.async.commit_group;" ::: "memory")
#define CP_WAIT(n)  asm volatile("cp.async.wait_group %0;" :: "n"(n) : "memory")

// ---------------- K0: split queue into bf16 hi/mid (packed k-pairs) ----------------
__global__ void k_qsplit(const float* __restrict__ queue) {
    int i = blockIdx.x * blockDim.x + threadIdx.x;
    if (i >= QSZ * DIM / 8) return;
    uint32_t oh[4], om[4];
    split8_bf16(queue + (size_t)i * 8, oh, om);
#pragma unroll
    for (int t = 0; t < 4; t++) {
        g_qh[(size_t)i * 4 + t] = oh[t];
        g_qm[(size_t)i * 4 + t] = om[t];
    }
}

// ---------------- K1: L2 normalize + bf16 hi/mid split ----------------
__global__ void k_normalize(const float* __restrict__ p1, const float* __restrict__ p2) {
    int gw   = (blockIdx.x * blockDim.x + threadIdx.x) >> 5;
    int lane = threadIdx.x & 31;
    if (gw >= 2 * BSZ) return;
    int input = gw >> 12;
    int row   = gw & (BSZ - 1);
    const float* src = (input ? p2 : p1) + (size_t)row * DIM;
    float4 v = ((const float4*)src)[lane];
    float s = v.x * v.x + v.y * v.y + v.z * v.z + v.w * v.w;
#pragma unroll
    for (int o = 16; o; o >>= 1) s += __shfl_xor_sync(0xffffffff, s, o);
    float inv = rsqrtf(s);
    float4 o4 = make_float4(v.x * inv, v.y * inv, v.z * inv, v.w * inv);
    ((float4*)(g_pn[input] + (size_t)row * DIM))[lane] = o4;
    uint32_t h0 = pack_bf16(o4.x, o4.y);
    uint32_t h1 = pack_bf16(o4.z, o4.w);
    uint32_t m0 = pack_bf16(o4.x - __uint_as_float(h0 << 16),
                            o4.y - __uint_as_float(h0 & 0xffff0000u));
    uint32_t m1 = pack_bf16(o4.z - __uint_as_float(h1 << 16),
                            o4.w - __uint_as_float(h1 & 0xffff0000u));
    uint2 hh = make_uint2(h0, h1), mm = make_uint2(m0, m1);
    ((uint2*)(g_pnh[input] + (size_t)row * 64))[lane] = hh;
    ((uint2*)(g_pnm[input] + (size_t)row * 64))[lane] = mm;
}

// ---------------- shared bf16 engine constants ----------------
#define A_WST   68                              // words per A row (64 data + 4 pad)
#define B_WST   20                              // words per B col (16 data + 4 pad)
#define A_WORDS (128 * A_WST)                   // 8704 per array
#define B_WORDS (256 * B_WST)                   // 5120 per array
#define BPAIRW  (2 * B_WORDS)                   // hi+mid one buffer

// ---------------- K2: 3-term bf16 m16n8k16 GEMM + running argmax ----------------
// grid (32, 2, 2), block 256 (8 warps: wm = wid&1, wn = wid>>1). BM=128, BN=256.
#define NN_SMEM_WORDS (2 * A_WORDS + 2 * BPAIRW + 512 + 512)
#define NN_SMEM_BYTES (NN_SMEM_WORDS * 4)       // 155,648 B

__global__ void __launch_bounds__(256, 1) k_nn() {
    extern __shared__ uint32_t smw[];
    uint32_t* Ah    = smw;                       // [128][68] words
    uint32_t* Am    = smw + A_WORDS;
    uint32_t* Bbase = smw + 2 * A_WORDS;         // buf j @ j*BPAIRW: hi @0, mid @+B_WORDS
    float*    sval  = (float*)(Bbase + 2 * BPAIRW);   // [128][4]
    int*      sidx  = (int*)(sval + 512);             // [128][4]
    uint32_t sb_B = smem_u32(Bbase);

    const int rb = blockIdx.x, input = blockIdx.y, qseg = blockIdx.z;
    const int tid = threadIdx.x, lane = tid & 31, wid = tid >> 5;
    const int wm = wid & 1, wn = wid >> 1;       // 2 x 4 warp grid
    const int gId = lane >> 2, tig = lane & 3;
    const size_t qbaseW = (size_t)qseg * QPART * (DIM / 2);

    const int NCH = (QPART / 256) * 4;           // 256 chunks (qt 64 x kk 4)

#define NN_COPY(c)                                                              \
    {                                                                           \
        int _qt = (c) >> 2, _klw = ((c) & 3) * 16;                              \
        uint32_t _base = sb_B + (uint32_t)(((c) & 1) * BPAIRW) * 4;             \
        _Pragma("unroll")                                                       \
        for (int _x = 0; _x < 8; _x++) {                                        \
            int _f = tid + _x * 256;                                            \
            int _arr = _f >> 10, _rem = _f & 1023;                              \
            int _r = _rem >> 2, _q = _rem & 3;                                  \
            const uint32_t* _sp = (_arr ? g_qm : g_qh) + qbaseW                 \
                + (size_t)(_qt * 256 + _r) * (DIM / 2) + _klw + _q * 4;         \
            uint32_t _dst = _base + (uint32_t)(_arr * B_WORDS + _r * B_WST + _q * 4) * 4; \
            cp16(_dst, _sp);                                                    \
        }                                                                       \
    }

    NN_COPY(0);
    CP_COMMIT();

    // ---- build bf16 hi/mid A in smem: 2 threads per row ----
    {
        int row = tid >> 1, half = tid & 1;
        const float* arow = g_pn[input] + ((size_t)rb * 128 + row) * DIM + half * 64;
        uint32_t wbase = row * A_WST + half * 32;
#pragma unroll
        for (int g = 0; g < 8; g++) {
            uint32_t oh[4], om[4];
            split8_bf16(arow + g * 8, oh, om);
#pragma unroll
            for (int t = 0; t < 4; t++) {
                Ah[wbase + g * 4 + t] = oh[t];
                Am[wbase + g * 4 + t] = om[t];
            }
        }
    }

    float best[8]; int bidx[8];
#pragma unroll
    for (int s = 0; s < 8; s++) { best[s] = -3.4e38f; bidx[s] = 0; }

#pragma unroll 1
    for (int qt = 0; qt < QPART / 256; qt++) {
        float c[4][8][4];
#pragma unroll
        for (int ma = 0; ma < 4; ma++)
#pragma unroll
            for (int na = 0; na < 8; na++)
#pragma unroll
                for (int r = 0; r < 4; r++) c[ma][na][r] = 0.f;

#pragma unroll 1
        for (int kk = 0; kk < 4; kk++) {
            int ch = qt * 4 + kk;
            if (ch + 1 < NCH) { NN_COPY(ch + 1); CP_COMMIT(); CP_WAIT(1); }
            else              { CP_WAIT(0); }
            __syncthreads();

            const uint32_t* bh = Bbase + (ch & 1) * BPAIRW;
            const uint32_t* bm = bh + B_WORDS;
#pragma unroll
            for (int ka = 0; ka < 2; ka++) {
                int kwB = ka * 8 + tig;
                int kwA = kk * 16 + kwB;
                uint32_t ah[4][4], am[4][4], bhf[8][2], bmf[8][2];
#pragma unroll
                for (int ma = 0; ma < 4; ma++) {
                    int rowA = wm * 64 + ma * 16 + gId;
                    ah[ma][0] = Ah[rowA * A_WST + kwA];
                    ah[ma][1] = Ah[(rowA + 8) * A_WST + kwA];
                    ah[ma][2] = Ah[rowA * A_WST + kwA + 4];
                    ah[ma][3] = Ah[(rowA + 8) * A_WST + kwA + 4];
                    am[ma][0] = Am[rowA * A_WST + kwA];
                    am[ma][1] = Am[(rowA + 8) * A_WST + kwA];
                    am[ma][2] = Am[rowA * A_WST + kwA + 4];
                    am[ma][3] = Am[(rowA + 8) * A_WST + kwA + 4];
                }
#pragma unroll
                for (int na = 0; na < 8; na++) {
                    int colB = wn * 64 + na * 8 + gId;
                    bhf[na][0] = bh[colB * B_WST + kwB];
                    bhf[na][1] = bh[colB * B_WST + kwB + 4];
                    bmf[na][0] = bm[colB * B_WST + kwB];
                    bmf[na][1] = bm[colB * B_WST + kwB + 4];
                }
#pragma unroll
                for (int ma = 0; ma < 4; ma++)
#pragma unroll
                    for (int na = 0; na < 8; na++)
                        mma_bf16(c[ma][na], ah[ma], bhf[na]);
#pragma unroll
                for (int ma = 0; ma < 4; ma++)
#pragma unroll
                    for (int na = 0; na < 8; na++)
                        mma_bf16(c[ma][na], ah[ma], bmf[na]);
#pragma unroll
                for (int ma = 0; ma < 4; ma++)
#pragma unroll
                    for (int na = 0; na < 8; na++)
                        mma_bf16(c[ma][na], am[ma], bhf[na]);
            }
            __syncthreads();
        }

        int colb = qseg * QPART + qt * 256 + wn * 64;
#pragma unroll
        for (int ma = 0; ma < 4; ma++) {
#pragma unroll
            for (int na = 0; na < 8; na++) {
                int cb = colb + na * 8 + 2 * tig;
#pragma unroll
                for (int r = 0; r < 4; r++) {
                    int slot = ma * 2 + (r >> 1);
                    float v = c[ma][na][r];
                    if (v > best[slot]) { best[slot] = v; bidx[slot] = cb + (r & 1); }
                }
            }
        }
    }

    __syncthreads();
#pragma unroll
    for (int s = 0; s < 8; s++) {
        float v = best[s]; int ix = bidx[s];
#pragma unroll
        for (int off = 1; off <= 2; off <<= 1) {
            float ov = __shfl_xor_sync(0xffffffff, v, off);
            int   oi = __shfl_xor_sync(0xffffffff, ix, off);
            if (ov > v || (ov == v && oi < ix)) { v = ov; ix = oi; }
        }
        if (tig == 0) {
            int row = wm * 64 + (s >> 1) * 16 + gId + ((s & 1) ? 8 : 0);
            sval[row * 4 + wn] = v;
            sidx[row * 4 + wn] = ix;
        }
    }
    __syncthreads();
    if (tid < 128) {
        float bv = -3.4e38f; int bi = 0x7fffffff;
#pragma unroll
        for (int w = 0; w < 4; w++) {
            float v = sval[tid * 4 + w]; int ix = sidx[tid * 4 + w];
            if (v > bv || (v == bv && ix < bi)) { bv = v; bi = ix; }
        }
        g_pval[input][qseg][rb * 128 + tid] = bv;
        g_pidx[input][qseg][rb * 128 + tid] = bi;
    }
}

// ---------------- K3: EXACT fp32 rescore of segment candidates + gather ----------------
__global__ void k_gather(const float* __restrict__ queue) {
    int gw   = (blockIdx.x * blockDim.x + threadIdx.x) >> 5;
    int lane = threadIdx.x & 31;
    if (gw >= 2 * BSZ) return;
    int input = gw >> 12, row = gw & (BSZ - 1);
    float4 p = ((const float4*)(g_pn[input] + (size_t)row * DIM))[lane];
    float bv = -3.4e38f; int bi = 0x7fffffff;
#pragma unroll
    for (int s = 0; s < QSPLIT; s++) {
        int idx = g_pidx[input][s][row];
        float4 q = ((const float4*)(queue + (size_t)idx * DIM))[lane];
        float d = p.x * q.x + p.y * q.y + p.z * q.z + p.w * q.w;
#pragma unroll
        for (int o = 16; o; o >>= 1) d += __shfl_xor_sync(0xffffffff, d, o);
        if (d > bv || (d == bv && idx < bi)) { bv = d; bi = idx; }
    }
    float4 q = ((const float4*)(queue + (size_t)bi * DIM))[lane];
    ((float4*)(g_nn[input] + (size_t)row * DIM))[lane] = q;
}

// ---------------- K4: logits via 3-term bf16 engine + fixed-shift exp partial sums ----------------
// grid (32, 2, LG_NSEG), block 256 (8 warps, wm=wid&1, wn=wid>>1). BM=128, BN=256, 8 tiles.
#define LG_SMEM_WORDS (2 * A_WORDS + 2 * BPAIRW + 256 + 512)
#define LG_SMEM_BYTES (LG_SMEM_WORDS * 4)        // ~154.6 KB

__global__ void __launch_bounds__(256, 1) k_logits() {
    extern __shared__ uint32_t smv[];
    uint32_t* Ah    = smv;                       // [128][68]
    uint32_t* Am    = smv + A_WORDS;
    uint32_t* Bbase = smv + 2 * A_WORDS;
    float*    scol  = (float*)(Bbase + 2 * BPAIRW);  // [256]
    float*    srow  = scol + 256;                     // [128][4]
    uint32_t sb_B = smem_u32(Bbase);

    const int rb = blockIdx.x, m = blockIdx.y, nseg = blockIdx.z;
    const int colbase = nseg * LG_COLS;
    const int tid = threadIdx.x, lane = tid & 31, wid = tid >> 5;
    const int wm = wid & 1, wn = wid >> 1;       // 2 x 4 warp grid
    const int gId = lane >> 2, tig = lane & 3;
    const uint32_t* Bh = g_pnh[1 - m];
    const uint32_t* Bm_ = g_pnm[1 - m];

    const int LNCH = (LG_COLS / 256) * 4;        // 32 chunks

#define LG_COPY(c)                                                              \
    {                                                                           \
        int _qt = (c) >> 2, _klw = ((c) & 3) * 16;                              \
        uint32_t _base = sb_B + (uint32_t)(((c) & 1) * BPAIRW) * 4;             \
        _Pragma("unroll")                                                       \
        for (int _x = 0; _x < 8; _x++) {                                        \
            int _f = tid + _x * 256;                                            \
            int _arr = _f >> 10, _rem = _f & 1023;                              \
            int _r = _rem >> 2, _q = _rem & 3;                                  \
            const uint32_t* _sp = (_arr ? Bm_ : Bh)                             \
                + (size_t)(colbase + _qt * 256 + _r) * (DIM / 2) + _klw + _q * 4; \
            uint32_t _dst = _base + (uint32_t)(_arr * B_WORDS + _r * B_WST + _q * 4) * 4; \
            cp16(_dst, _sp);                                                    \
        }                                                                       \
    }

    LG_COPY(0);
    CP_COMMIT();

    // A = g_nn[m] rows, bf16 split in smem (2 threads/row)
    {
        int row = tid >> 1, half = tid & 1;
        const float* arow = g_nn[m] + ((size_t)rb * 128 + row) * DIM + half * 64;
        uint32_t wbase = row * A_WST + half * 32;
#pragma unroll
        for (int g = 0; g < 8; g++) {
            uint32_t oh[4], om[4];
            split8_bf16(arow + g * 8, oh, om);
#pragma unroll
            for (int t = 0; t < 4; t++) {
                Ah[wbase + g * 4 + t] = oh[t];
                Am[wbase + g * 4 + t] = om[t];
            }
        }
    }
    scol[tid] = 0.f;

    float rs[8];
#pragma unroll
    for (int s = 0; s < 8; s++) rs[s] = 0.f;

#pragma unroll 1
    for (int qt = 0; qt < LG_COLS / 256; qt++) {
        float c[4][8][4];
#pragma unroll
        for (int ma = 0; ma < 4; ma++)
#pragma unroll
            for (int na = 0; na < 8; na++)
#pragma unroll
                for (int r = 0; r < 4; r++) c[ma][na][r] = 0.f;

#pragma unroll 1
        for (int kk = 0; kk < 4; kk++) {
            int ch = qt * 4 + kk;
            if (ch + 1 < LNCH) { LG_COPY(ch + 1); CP_COMMIT(); CP_WAIT(1); }
            else               { CP_WAIT(0); }
            __syncthreads();

            const uint32_t* bh = Bbase + (ch & 1) * BPAIRW;
            const uint32_t* bm = bh + B_WORDS;
#pragma unroll
            for (int ka = 0; ka < 2; ka++) {
                int kwB = ka * 8 + tig;
                int kwA = kk * 16 + kwB;
                uint32_t ah[4][4], am[4][4], bhf[8][2], bmf[8][2];
#pragma unroll
                for (int ma = 0; ma < 4; ma++) {
                    int rowA = wm * 64 + ma * 16 + gId;
                    ah[ma][0] = Ah[rowA * A_WST + kwA];
                    ah[ma][1] = Ah[(rowA + 8) * A_WST + kwA];
                    ah[ma][2] = Ah[rowA * A_WST + kwA + 4];
                    ah[ma][3] = Ah[(rowA + 8) * A_WST + kwA + 4];
                    am[ma][0] = Am[rowA * A_WST + kwA];
                    am[ma][1] = Am[(rowA + 8) * A_WST + kwA];
                    am[ma][2] = Am[rowA * A_WST + kwA + 4];
                    am[ma][3] = Am[(rowA + 8) * A_WST + kwA + 4];
                }
#pragma unroll
                for (int na = 0; na < 8; na++) {
                    int colB = wn * 64 + na * 8 + gId;
                    bhf[na][0] = bh[colB * B_WST + kwB];
                    bhf[na][1] = bh[colB * B_WST + kwB + 4];
                    bmf[na][0] = bm[colB * B_WST + kwB];
                    bmf[na][1] = bm[colB * B_WST + kwB + 4];
                }
#pragma unroll
                for (int ma = 0; ma < 4; ma++)
#pragma unroll
                    for (int na = 0; na < 8; na++)
                        mma_bf16(c[ma][na], ah[ma], bhf[na]);
#pragma unroll
                for (int ma = 0; ma < 4; ma++)
#pragma unroll
                    for (int na = 0; na < 8; na++)
                        mma_bf16(c[ma][na], ah[ma], bmf[na]);
#pragma unroll
                for (int ma = 0; ma < 4; ma++)
#pragma unroll
                    for (int na = 0; na < 8; na++)
                        mma_bf16(c[ma][na], am[ma], bhf[na]);
            }
            __syncthreads();
        }

        // epilogue: l = c*10; e = exp(l-10); row + col partial sums; diag
        float ctmp[8][2];
#pragma unroll
        for (int na = 0; na < 8; na++) { ctmp[na][0] = 0.f; ctmp[na][1] = 0.f; }
        int gcol0 = colbase + qt * 256 + wn * 64;
#pragma unroll
        for (int ma = 0; ma < 4; ma++) {
#pragma unroll
            for (int na = 0; na < 8; na++) {
#pragma unroll
                for (int r = 0; r < 4; r++) {
                    float l = c[ma][na][r] * INV_T;
                    float e = __expf(l - SHIFT);
                    rs[ma * 2 + (r >> 1)] += e;
                    ctmp[na][r & 1] += e;
                    int grow = rb * 128 + wm * 64 + ma * 16 + gId + (r >> 1) * 8;
                    int gcol = gcol0 + na * 8 + 2 * tig + (r & 1);
                    if (gcol == grow) g_diag[m][grow] = l;
                }
            }
        }
#pragma unroll
        for (int na = 0; na < 8; na++)
#pragma unroll
            for (int r = 0; r < 2; r++) {
#pragma unroll
                for (int off = 4; off <= 16; off <<= 1)
                    ctmp[na][r] += __shfl_xor_sync(0xffffffff, ctmp[na][r], off);
            }
        if (gId == 0) {
#pragma unroll
            for (int na = 0; na < 8; na++) {
                atomicAdd(&scol[wn * 64 + na * 8 + 2 * tig + 0], ctmp[na][0]);
                atomicAdd(&scol[wn * 64 + na * 8 + 2 * tig + 1], ctmp[na][1]);
            }
        }
        __syncthreads();
        g_colpart[m][rb][colbase + qt * 256 + tid] = scol[tid];
        scol[tid] = 0.f;
        // next tile's first chunk __syncthreads orders this reset before new atomics
    }

    // row sums: reduce over tig, then over 4 wn warps via smem
#pragma unroll
    for (int s = 0; s < 8; s++) {
#pragma unroll
        for (int off = 1; off <= 2; off <<= 1)
            rs[s] += __shfl_xor_sync(0xffffffff, rs[s], off);
        if (tig == 0) {
            int row = wm * 64 + (s >> 1) * 16 + gId + ((s & 1) ? 8 : 0);
            srow[row * 4 + wn] = rs[s];
        }
    }
    __syncthreads();
    if (tid < 128)
        g_rowpart[m][nseg][rb * 128 + tid] =
            srow[tid * 4] + srow[tid * 4 + 1] + srow[tid * 4 + 2] + srow[tid * 4 + 3];
}

// ---------------- K5: final losses from partials ----------------
__global__ void k_loss(float* __restrict__ out) {
    int g = blockIdx.x * blockDim.x + threadIdx.x;
    if (g >= 2 * BSZ) return;
    int m = g >> 12, i = g & (BSZ - 1);
    float rsum = 0.f, csum = 0.f;
#pragma unroll
    for (int s = 0; s < LG_NSEG; s++) rsum += g_rowpart[m][s][i];
#pragma unroll 8
    for (int rb = 0; rb < 32; rb++) csum += g_colpart[m][rb][i];
    float d = g_diag[m][i];
    out[(size_t)(2 * m) * BSZ + i]     = SHIFT + logf(rsum) - d;
    out[(size_t)(2 * m + 1) * BSZ + i] = SHIFT + logf(csum) - d;
}

// ---------------- launch ----------------
extern "C" void kernel_launch(void* const* d_in, const int* in_sizes, int n_in,
                              void* d_out, int out_size) {
    const float *p1 = nullptr, *p2 = nullptr, *queue = nullptr;
    for (int i = 0; i < n_in; i++) {
        if (in_sizes[i] == QSZ * DIM) queue = (const float*)d_in[i];
        else if (!p1) p1 = (const float*)d_in[i];
        else p2 = (const float*)d_in[i];
    }
    float* out = (float*)d_out;

    cudaFuncSetAttribute(k_nn, cudaFuncAttributeMaxDynamicSharedMemorySize, NN_SMEM_BYTES);
    cudaFuncSetAttribute(k_logits, cudaFuncAttributeMaxDynamicSharedMemorySize, LG_SMEM_BYTES);

    k_normalize<<<(2 * BSZ * 32 + 255) / 256, 256>>>(p1, p2);
    k_qsplit<<<(QSZ * DIM / 8 + 255) / 256, 256>>>(queue);

    dim3 g2(BSZ / 128, 2, QSPLIT);
    k_nn<<<g2, 256, NN_SMEM_BYTES>>>();

    k_gather<<<(2 * BSZ * 32 + 255) / 256, 256>>>(queue);

    dim3 g4(BSZ / 128, 2, LG_NSEG);
    k_logits<<<g4, 256, LG_SMEM_BYTES>>>();

    k_loss<<<(2 * BSZ + 255) / 256, 256>>>(out);
}

// round 15
// speedup vs baseline: 2.8398x; 1.3503x over previous
#include <cuda_runtime.h>
#include <math.h>
#include <stdint.h>

#define BSZ   4096
#define QSZ   32768
#define DIM   128
#define QSPLIT 2
#define QPART (QSZ / QSPLIT)   // 16384
#define NBLK  (QSZ / 64)       // 512 column blocks of 64
#define MARGIN 0.01f
#define LG_NSEG  2
#define LG_COLS  (BSZ / LG_NSEG) // 2048

#define INV_T 10.0f
#define SHIFT 10.0f

// ---------------- scratch (static device globals; no allocation) ----------------
__device__ float    g_pn [2][BSZ * DIM];
__device__ uint32_t g_pnh[2][BSZ * DIM / 2];  // p normalized, bf16-hi packed pairs
__device__ uint32_t g_pnm[2][BSZ * DIM / 2];  // bf16-mid
__device__ float    g_nn [2][BSZ * DIM];
__device__ uint32_t g_qh [QSZ * DIM / 2];     // queue bf16-hi packed pairs (8 MB)
__device__ float    g_bmax[2][BSZ][NBLK];     // per-row per-64col-block approx max (16 MB)
__device__ float    g_rowpart[2][LG_NSEG][BSZ];
__device__ float    g_colpart[2][32][BSZ];
__device__ float    g_diag[2][BSZ];

// ---------------- helpers ----------------
__device__ __forceinline__ uint32_t smem_u32(const void* p) {
    uint32_t a;
    asm("{ .reg .u64 t; cvta.to.shared.u64 t, %1; cvt.u32.u64 %0, t; }" : "=r"(a) : "l"(p));
    return a;
}
__device__ __forceinline__ void mma_bf16(float c[4], const uint32_t a[4], const uint32_t b[2]) {
    asm volatile(
        "mma.sync.aligned.m16n8k16.row.col.f32.bf16.bf16.f32 "
        "{%0,%1,%2,%3}, {%4,%5,%6,%7}, {%8,%9}, {%0,%1,%2,%3};\n"
        : "+f"(c[0]), "+f"(c[1]), "+f"(c[2]), "+f"(c[3])
        : "r"(a[0]), "r"(a[1]), "r"(a[2]), "r"(a[3]), "r"(b[0]), "r"(b[1]));
}
__device__ __forceinline__ uint32_t pack_bf16(float lo, float hi_) {
    uint32_t r;
    asm("cvt.rn.bf16x2.f32 %0, %1, %2;" : "=r"(r) : "f"(hi_), "f"(lo));
    return r;
}
__device__ __forceinline__ void split8_bf16(const float* p, uint32_t oh[4], uint32_t om[4]) {
#pragma unroll
    for (int t = 0; t < 4; t++) {
        float f0 = p[2 * t], f1 = p[2 * t + 1];
        uint32_t h = pack_bf16(f0, f1);
        float h0 = __uint_as_float(h << 16);
        float h1 = __uint_as_float(h & 0xffff0000u);
        oh[t] = h;
        om[t] = pack_bf16(f0 - h0, f1 - h1);
    }
}
__device__ __forceinline__ void hi8_bf16(const float* p, uint32_t oh[4]) {
#pragma unroll
    for (int t = 0; t < 4; t++) oh[t] = pack_bf16(p[2 * t], p[2 * t + 1]);
}
__device__ __forceinline__ void cp16(uint32_t dst, const void* src) {
    asm volatile("cp.async.cg.shared.global [%0], [%1], 16;" :: "r"(dst), "l"(src) : "memory");
}
#define CP_COMMIT() asm volatile("cp.async.commit_group;" ::: "memory")
#define CP_WAIT(n)  asm volatile("cp.async.wait_group %0;" :: "n"(n) : "memory")

// ---------------- K0: queue -> bf16-hi packed pairs ----------------
__global__ void k_qsplit(const float* __restrict__ queue) {
    int i = blockIdx.x * blockDim.x + threadIdx.x;
    if (i >= QSZ * DIM / 8) return;
    uint32_t oh[4];
    hi8_bf16(queue + (size_t)i * 8, oh);
#pragma unroll
    for (int t = 0; t < 4; t++) g_qh[(size_t)i * 4 + t] = oh[t];
}

// ---------------- K1: L2 normalize + bf16 hi/mid split (for k_logits) ----------------
__global__ void k_normalize(const float* __restrict__ p1, const float* __restrict__ p2) {
    int gw   = (blockIdx.x * blockDim.x + threadIdx.x) >> 5;
    int lane = threadIdx.x & 31;
    if (gw >= 2 * BSZ) return;
    int input = gw >> 12;
    int row   = gw & (BSZ - 1);
    const float* src = (input ? p2 : p1) + (size_t)row * DIM;
    float4 v = ((const float4*)src)[lane];
    float s = v.x * v.x + v.y * v.y + v.z * v.z + v.w * v.w;
#pragma unroll
    for (int o = 16; o; o >>= 1) s += __shfl_xor_sync(0xffffffff, s, o);
    float inv = rsqrtf(s);
    float4 o4 = make_float4(v.x * inv, v.y * inv, v.z * inv, v.w * inv);
    ((float4*)(g_pn[input] + (size_t)row * DIM))[lane] = o4;
    uint32_t h0 = pack_bf16(o4.x, o4.y);
    uint32_t h1 = pack_bf16(o4.z, o4.w);
    uint32_t m0 = pack_bf16(o4.x - __uint_as_float(h0 << 16),
                            o4.y - __uint_as_float(h0 & 0xffff0000u));
    uint32_t m1 = pack_bf16(o4.z - __uint_as_float(h1 << 16),
                            o4.w - __uint_as_float(h1 & 0xffff0000u));
    ((uint2*)(g_pnh[input] + (size_t)row * 64))[lane] = make_uint2(h0, h1);
    ((uint2*)(g_pnm[input] + (size_t)row * 64))[lane] = make_uint2(m0, m1);
}

// ---------------- shared bf16 engine constants ----------------
#define A_WST   68
#define B_WST   20
#define A_WORDS (128 * A_WST)                   // 8704
#define B_WORDS (256 * B_WST)                   // 5120

// ---------------- K2: 1-term bf16 GEMM + per-64col-block max ----------------
// grid (32, 2, 2), block 256 (8 warps: wm = wid&1, wn = wid>>1). BM=128, BN=256.
#define NN_SMEM_WORDS (A_WORDS + 2 * B_WORDS)
#define NN_SMEM_BYTES (NN_SMEM_WORDS * 4)       // 75,776 B

__global__ void __launch_bounds__(256, 1) k_nn() {
    extern __shared__ uint32_t smw[];
    uint32_t* Ah    = smw;                       // [128][68] words
    uint32_t* Bbase = smw + A_WORDS;             // buf j @ j*B_WORDS (hi only)
    uint32_t sb_B = smem_u32(Bbase);

    const int rb = blockIdx.x, input = blockIdx.y, qseg = blockIdx.z;
    const int tid = threadIdx.x, lane = tid & 31, wid = tid >> 5;
    const int wm = wid & 1, wn = wid >> 1;       // 2 x 4 warp grid
    const int gId = lane >> 2, tig = lane & 3;
    const size_t qbaseW = (size_t)qseg * QPART * (DIM / 2);

    const int NCH = (QPART / 256) * 4;           // 256 chunks (qt 64 x kk 4)

    // cp.async copy chunk c (256 cols x 32 k of hi) into buffer c&1: 4 cp16/thread
#define NN_COPY(c)                                                              \
    {                                                                           \
        int _qt = (c) >> 2, _klw = ((c) & 3) * 16;                              \
        uint32_t _base = sb_B + (uint32_t)(((c) & 1) * B_WORDS) * 4;            \
        _Pragma("unroll")                                                       \
        for (int _x = 0; _x < 4; _x++) {                                        \
            int _f = tid + _x * 256;                                            \
            int _r = _f >> 2, _q = _f & 3;                                      \
            const uint32_t* _sp = g_qh + qbaseW                                 \
                + (size_t)(_qt * 256 + _r) * (DIM / 2) + _klw + _q * 4;         \
            uint32_t _dst = _base + (uint32_t)(_r * B_WST + _q * 4) * 4;        \
            cp16(_dst, _sp);                                                    \
        }                                                                       \
    }

    NN_COPY(0);
    CP_COMMIT();

    // build bf16-hi A in smem: 2 threads per row
    {
        int row = tid >> 1, half = tid & 1;
        const float* arow = g_pn[input] + ((size_t)rb * 128 + row) * DIM + half * 64;
        uint32_t wbase = row * A_WST + half * 32;
#pragma unroll
        for (int g = 0; g < 8; g++) {
            uint32_t oh[4];
            hi8_bf16(arow + g * 8, oh);
#pragma unroll
            for (int t = 0; t < 4; t++) Ah[wbase + g * 4 + t] = oh[t];
        }
    }

#pragma unroll 1
    for (int qt = 0; qt < QPART / 256; qt++) {
        float c[4][8][4];
#pragma unroll
        for (int ma = 0; ma < 4; ma++)
#pragma unroll
            for (int na = 0; na < 8; na++)
#pragma unroll
                for (int r = 0; r < 4; r++) c[ma][na][r] = 0.f;

#pragma unroll 1
        for (int kk = 0; kk < 4; kk++) {
            int ch = qt * 4 + kk;
            if (ch + 1 < NCH) { NN_COPY(ch + 1); CP_COMMIT(); CP_WAIT(1); }
            else              { CP_WAIT(0); }
            __syncthreads();

            const uint32_t* bh = Bbase + (ch & 1) * B_WORDS;
#pragma unroll
            for (int ka = 0; ka < 2; ka++) {
                int kwB = ka * 8 + tig;
                int kwA = kk * 16 + kwB;
                uint32_t ah[4][4], bhf[8][2];
#pragma unroll
                for (int ma = 0; ma < 4; ma++) {
                    int rowA = wm * 64 + ma * 16 + gId;
                    ah[ma][0] = Ah[rowA * A_WST + kwA];
                    ah[ma][1] = Ah[(rowA + 8) * A_WST + kwA];
                    ah[ma][2] = Ah[rowA * A_WST + kwA + 4];
                    ah[ma][3] = Ah[(rowA + 8) * A_WST + kwA + 4];
                }
#pragma unroll
                for (int na = 0; na < 8; na++) {
                    int colB = wn * 64 + na * 8 + gId;
                    bhf[na][0] = bh[colB * B_WST + kwB];
                    bhf[na][1] = bh[colB * B_WST + kwB + 4];
                }
#pragma unroll
                for (int ma = 0; ma < 4; ma++)
#pragma unroll
                    for (int na = 0; na < 8; na++)
                        mma_bf16(c[ma][na], ah[ma], bhf[na]);
            }
            __syncthreads();
        }

        // per-row block max over this warp's 64 cols -> g_bmax
        float sl[8];
#pragma unroll
        for (int s = 0; s < 8; s++) sl[s] = -3.4e38f;
#pragma unroll
        for (int ma = 0; ma < 4; ma++)
#pragma unroll
            for (int na = 0; na < 8; na++)
#pragma unroll
                for (int r = 0; r < 4; r++) {
                    int s = ma * 2 + (r >> 1);
                    if (c[ma][na][r] > sl[s]) sl[s] = c[ma][na][r];
                }
        int gb = qseg * 256 + qt * 4 + wn;
#pragma unroll
        for (int s = 0; s < 8; s++) {
            float v = sl[s];
            v = fmaxf(v, __shfl_xor_sync(0xffffffff, v, 1));
            v = fmaxf(v, __shfl_xor_sync(0xffffffff, v, 2));
            if (tig == 0) {
                int row = rb * 128 + wm * 64 + (s >> 1) * 16 + gId + ((s & 1) ? 8 : 0);
                g_bmax[input][row][gb] = v;
            }
        }
    }
}

// ---------------- K3: margin filter + EXACT fp32 rescore + gather ----------------
// One warp per (input,row). Guaranteed: 1-term error <= 2*2^-9 < MARGIN/2, so the
// true NN's block always passes the filter; its exact dot wins the exact compare.
__global__ void k_rescore(const float* __restrict__ queue) {
    __shared__ float4 sp4[8][32];
    int gw   = (blockIdx.x * blockDim.x + threadIdx.x) >> 5;
    int lane = threadIdx.x & 31;
    if (gw >= 2 * BSZ) return;
    int input = gw >> 12, row = gw & (BSZ - 1);
    int w = (threadIdx.x >> 5);

    float4 p = ((const float4*)(g_pn[input] + (size_t)row * DIM))[lane];
    sp4[w][lane] = p;
    __syncwarp();

    // load 512 block maxes, find global max
    float bm[16];
    float mx = -3.4e38f;
#pragma unroll
    for (int i = 0; i < 16; i++) {
        bm[i] = g_bmax[input][row][lane + 32 * i];
        mx = fmaxf(mx, bm[i]);
    }
#pragma unroll
    for (int o = 16; o; o >>= 1) mx = fmaxf(mx, __shfl_xor_sync(0xffffffff, mx, o));
    float thr = mx - MARGIN;

    float bestv = -3.4e38f;
    int   besti = 0x7fffffff;
#pragma unroll 1
    for (int i = 0; i < 16; i++) {
        unsigned msk = __ballot_sync(0xffffffff, bm[i] >= thr);
        while (msk) {
            int b = __ffs(msk) - 1;
            msk &= msk - 1;
            int colbase = (b + 32 * i) * 64;
#pragma unroll
            for (int cc = 0; cc < 2; cc++) {
                int col = colbase + lane + cc * 32;
                const float4* q4 = (const float4*)(queue + (size_t)col * DIM);
                float d = 0.f;
#pragma unroll
                for (int j = 0; j < 32; j++) {
                    float4 qv = q4[j];
                    float4 pv = sp4[w][j];
                    d += qv.x * pv.x + qv.y * pv.y + qv.z * pv.z + qv.w * pv.w;
                }
                if (d > bestv || (d == bestv && col < besti)) { bestv = d; besti = col; }
            }
        }
    }
    // warp reduce (max, min-index tie)
#pragma unroll
    for (int o = 16; o; o >>= 1) {
        float ov = __shfl_xor_sync(0xffffffff, bestv, o);
        int   oi = __shfl_xor_sync(0xffffffff, besti, o);
        if (ov > bestv || (ov == bestv && oi < besti)) { bestv = ov; besti = oi; }
    }
    float4 qv = ((const float4*)(queue + (size_t)besti * DIM))[lane];
    ((float4*)(g_nn[input] + (size_t)row * DIM))[lane] = qv;
}

// ---------------- K4: logits via 3-term bf16 engine + fixed-shift exp partial sums ----------------
#define BPAIRW (2 * B_WORDS)
#define LG_SMEM_WORDS (2 * A_WORDS + 2 * BPAIRW + 256 + 512)
#define LG_SMEM_BYTES (LG_SMEM_WORDS * 4)

__global__ void __launch_bounds__(256, 1) k_logits() {
    extern __shared__ uint32_t smv[];
    uint32_t* Ah    = smv;                       // [128][68]
    uint32_t* Am    = smv + A_WORDS;
    uint32_t* Bbase = smv + 2 * A_WORDS;
    float*    scol  = (float*)(Bbase + 2 * BPAIRW);  // [256]
    float*    srow  = scol + 256;                     // [128][4]
    uint32_t sb_B = smem_u32(Bbase);

    const int rb = blockIdx.x, m = blockIdx.y, nseg = blockIdx.z;
    const int colbase = nseg * LG_COLS;
    const int tid = threadIdx.x, lane = tid & 31, wid = tid >> 5;
    const int wm = wid & 1, wn = wid >> 1;
    const int gId = lane >> 2, tig = lane & 3;
    const uint32_t* Bh = g_pnh[1 - m];
    const uint32_t* Bm_ = g_pnm[1 - m];

    const int LNCH = (LG_COLS / 256) * 4;        // 32 chunks

#define LG_COPY(c)                                                              \
    {                                                                           \
        int _qt = (c) >> 2, _klw = ((c) & 3) * 16;                              \
        uint32_t _base = sb_B + (uint32_t)(((c) & 1) * BPAIRW) * 4;             \
        _Pragma("unroll")                                                       \
        for (int _x = 0; _x < 8; _x++) {                                        \
            int _f = tid + _x * 256;                                            \
            int _arr = _f >> 10, _rem = _f & 1023;                              \
            int _r = _rem >> 2, _q = _rem & 3;                                  \
            const uint32_t* _sp = (_arr ? Bm_ : Bh)                             \
                + (size_t)(colbase + _qt * 256 + _r) * (DIM / 2) + _klw + _q * 4; \
            uint32_t _dst = _base + (uint32_t)(_arr * B_WORDS + _r * B_WST + _q * 4) * 4; \
            cp16(_dst, _sp);                                                    \
        }                                                                       \
    }

    LG_COPY(0);
    CP_COMMIT();

    {
        int row = tid >> 1, half = tid & 1;
        const float* arow = g_nn[m] + ((size_t)rb * 128 + row) * DIM + half * 64;
        uint32_t wbase = row * A_WST + half * 32;
#pragma unroll
        for (int g = 0; g < 8; g++) {
            uint32_t oh[4], om[4];
            split8_bf16(arow + g * 8, oh, om);
#pragma unroll
            for (int t = 0; t < 4; t++) {
                Ah[wbase + g * 4 + t] = oh[t];
                Am[wbase + g * 4 + t] = om[t];
            }
        }
    }
    scol[tid] = 0.f;

    float rs[8];
#pragma unroll
    for (int s = 0; s < 8; s++) rs[s] = 0.f;

#pragma unroll 1
    for (int qt = 0; qt < LG_COLS / 256; qt++) {
        float c[4][8][4];
#pragma unroll
        for (int ma = 0; ma < 4; ma++)
#pragma unroll
            for (int na = 0; na < 8; na++)
#pragma unroll
                for (int r = 0; r < 4; r++) c[ma][na][r] = 0.f;

#pragma unroll 1
        for (int kk = 0; kk < 4; kk++) {
            int ch = qt * 4 + kk;
            if (ch + 1 < LNCH) { LG_COPY(ch + 1); CP_COMMIT(); CP_WAIT(1); }
            else               { CP_WAIT(0); }
            __syncthreads();

            const uint32_t* bh = Bbase + (ch & 1) * BPAIRW;
            const uint32_t* bm = bh + B_WORDS;
#pragma unroll
            for (int ka = 0; ka < 2; ka++) {
                int kwB = ka * 8 + tig;
                int kwA = kk * 16 + kwB;
                uint32_t ah[4][4], am[4][4], bhf[8][2], bmf[8][2];
#pragma unroll
                for (int ma = 0; ma < 4; ma++) {
                    int rowA = wm * 64 + ma * 16 + gId;
                    ah[ma][0] = Ah[rowA * A_WST + kwA];
                    ah[ma][1] = Ah[(rowA + 8) * A_WST + kwA];
                    ah[ma][2] = Ah[rowA * A_WST + kwA + 4];
                    ah[ma][3] = Ah[(rowA + 8) * A_WST + kwA + 4];
                    am[ma][0] = Am[rowA * A_WST + kwA];
                    am[ma][1] = Am[(rowA + 8) * A_WST + kwA];
                    am[ma][2] = Am[rowA * A_WST + kwA + 4];
                    am[ma][3] = Am[(rowA + 8) * A_WST + kwA + 4];
                }
#pragma unroll
                for (int na = 0; na < 8; na++) {
                    int colB = wn * 64 + na * 8 + gId;
                    bhf[na][0] = bh[colB * B_WST + kwB];
                    bhf[na][1] = bh[colB * B_WST + kwB + 4];
                    bmf[na][0] = bm[colB * B_WST + kwB];
                    bmf[na][1] = bm[colB * B_WST + kwB + 4];
                }
#pragma unroll
                for (int ma = 0; ma < 4; ma++)
#pragma unroll
                    for (int na = 0; na < 8; na++)
                        mma_bf16(c[ma][na], ah[ma], bhf[na]);
#pragma unroll
                for (int ma = 0; ma < 4; ma++)
#pragma unroll
                    for (int na = 0; na < 8; na++)
                        mma_bf16(c[ma][na], ah[ma], bmf[na]);
#pragma unroll
                for (int ma = 0; ma < 4; ma++)
#pragma unroll
                    for (int na = 0; na < 8; na++)
                        mma_bf16(c[ma][na], am[ma], bhf[na]);
            }
            __syncthreads();
        }

        float ctmp[8][2];
#pragma unroll
        for (int na = 0; na < 8; na++) { ctmp[na][0] = 0.f; ctmp[na][1] = 0.f; }
        int gcol0 = colbase + qt * 256 + wn * 64;
#pragma unroll
        for (int ma = 0; ma < 4; ma++) {
#pragma unroll
            for (int na = 0; na < 8; na++) {
#pragma unroll
                for (int r = 0; r < 4; r++) {
                    float l = c[ma][na][r] * INV_T;
                    float e = __expf(l - SHIFT);
                    rs[ma * 2 + (r >> 1)] += e;
                    ctmp[na][r & 1] += e;
                    int grow = rb * 128 + wm * 64 + ma * 16 + gId + (r >> 1) * 8;
                    int gcol = gcol0 + na * 8 + 2 * tig + (r & 1);
                    if (gcol == grow) g_diag[m][grow] = l;
                }
            }
        }
#pragma unroll
        for (int na = 0; na < 8; na++)
#pragma unroll
            for (int r = 0; r < 2; r++) {
#pragma unroll
                for (int off = 4; off <= 16; off <<= 1)
                    ctmp[na][r] += __shfl_xor_sync(0xffffffff, ctmp[na][r], off);
            }
        if (gId == 0) {
#pragma unroll
            for (int na = 0; na < 8; na++) {
                atomicAdd(&scol[wn * 64 + na * 8 + 2 * tig + 0], ctmp[na][0]);
                atomicAdd(&scol[wn * 64 + na * 8 + 2 * tig + 1], ctmp[na][1]);
            }
        }
        __syncthreads();
        g_colpart[m][rb][colbase + qt * 256 + tid] = scol[tid];
        scol[tid] = 0.f;
    }

#pragma unroll
    for (int s = 0; s < 8; s++) {
#pragma unroll
        for (int off = 1; off <= 2; off <<= 1)
            rs[s] += __shfl_xor_sync(0xffffffff, rs[s], off);
        if (tig == 0) {
            int row = wm * 64 + (s >> 1) * 16 + gId + ((s & 1) ? 8 : 0);
            srow[row * 4 + wn] = rs[s];
        }
    }
    __syncthreads();
    if (tid < 128)
        g_rowpart[m][nseg][rb * 128 + tid] =
            srow[tid * 4] + srow[tid * 4 + 1] + srow[tid * 4 + 2] + srow[tid * 4 + 3];
}

// ---------------- K5: final losses from partials ----------------
__global__ void k_loss(float* __restrict__ out) {
    int g = blockIdx.x * blockDim.x + threadIdx.x;
    if (g >= 2 * BSZ) return;
    int m = g >> 12, i = g & (BSZ - 1);
    float rsum = 0.f, csum = 0.f;
#pragma unroll
    for (int s = 0; s < LG_NSEG; s++) rsum += g_rowpart[m][s][i];
#pragma unroll 8
    for (int rb = 0; rb < 32; rb++) csum += g_colpart[m][rb][i];
    float d = g_diag[m][i];
    out[(size_t)(2 * m) * BSZ + i]     = SHIFT + logf(rsum) - d;
    out[(size_t)(2 * m + 1) * BSZ + i] = SHIFT + logf(csum) - d;
}

// ---------------- launch ----------------
extern "C" void kernel_launch(void* const* d_in, const int* in_sizes, int n_in,
                              void* d_out, int out_size) {
    const float *p1 = nullptr, *p2 = nullptr, *queue = nullptr;
    for (int i = 0; i < n_in; i++) {
        if (in_sizes[i] == QSZ * DIM) queue = (const float*)d_in[i];
        else if (!p1) p1 = (const float*)d_in[i];
        else p2 = (const float*)d_in[i];
    }
    float* out = (float*)d_out;

    cudaFuncSetAttribute(k_nn, cudaFuncAttributeMaxDynamicSharedMemorySize, NN_SMEM_BYTES);
    cudaFuncSetAttribute(k_logits, cudaFuncAttributeMaxDynamicSharedMemorySize, LG_SMEM_BYTES);

    k_normalize<<<(2 * BSZ * 32 + 255) / 256, 256>>>(p1, p2);
    k_qsplit<<<(QSZ * DIM / 8 + 255) / 256, 256>>>(queue);

    dim3 g2(BSZ / 128, 2, QSPLIT);
    k_nn<<<g2, 256, NN_SMEM_BYTES>>>();

    k_rescore<<<(2 * BSZ * 32 + 255) / 256, 256>>>(queue);

    dim3 g4(BSZ / 128, 2, LG_NSEG);
    k_logits<<<g4, 256, LG_SMEM_BYTES>>>();

    k_loss<<<(2 * BSZ + 255) / 256, 256>>>(out);
}